// round 13
// baseline (speedup 1.0000x reference)
#include <cuda_runtime.h>
#include <cuda_bf16.h>
#include <cstdint>

// ---------------- problem constants ----------------
constexpr int Bsz   = 16;
constexpr int Hdim  = 112;
constexpr int Wdim  = 112;
constexpr int Cc    = 128;
constexpr int HEADS = 4;
constexpr int HD    = 32;
constexpr int WS    = 7;
constexpr int L     = Hdim * Wdim;        // 12544
constexpr int T     = Bsz * L;            // 200704
constexpr int NTOK  = WS * WS;            // 49
constexpr int WPB   = (Hdim / WS) * (Wdim / WS);  // 256
constexpr int NWIN  = Bsz * WPB;          // 4096
constexpr int MLPH  = 512;
constexpr float SCALE = 0.17677669529663687f;
constexpr float EPS   = 1e-5f;

// ---------------- device scratch ----------------
__device__ __align__(16) __nv_bfloat16 g_xn[T * Cc];
__device__ __align__(16) __nv_bfloat16 g_vn[T * Cc];
__device__ __align__(16) __nv_bfloat16 g_q [T * Cc];
__device__ __align__(16) __nv_bfloat16 g_k [T * Cc];
__device__ __align__(16) __nv_bfloat16 g_v [T * Cc];
__device__ __align__(16) __nv_bfloat16 g_ao[T * Cc];
__device__ __align__(16) float         g_xo[T * Cc];
__device__ __align__(16) __nv_bfloat16 g_xon[T * Cc];
__device__ __align__(16) __nv_bfloat16 g_h1[(size_t)T * MLPH];
__device__ __align__(16) __nv_bfloat16 g_qw [Cc * Cc];
__device__ __align__(16) __nv_bfloat16 g_kvw[2 * Cc * Cc];
__device__ __align__(16) __nv_bfloat16 g_pw [Cc * Cc];
__device__ __align__(16) __nv_bfloat16 g_f1w[MLPH * Cc];
__device__ __align__(16) __nv_bfloat16 g_f2w[Cc * MLPH];

// ---------------- helpers ----------------
__device__ __forceinline__ uint32_t s2u(const void* p) {
    return (uint32_t)__cvta_generic_to_shared(p);
}
__device__ __forceinline__ void ldsm4(uint32_t& r0, uint32_t& r1, uint32_t& r2,
                                      uint32_t& r3, uint32_t addr) {
    asm volatile("ldmatrix.sync.aligned.m8n8.x4.shared.b16 {%0,%1,%2,%3},[%4];"
                 : "=r"(r0), "=r"(r1), "=r"(r2), "=r"(r3) : "r"(addr));
}
__device__ __forceinline__ void cpasync16(uint32_t dst, const void* src) {
    asm volatile("cp.async.cg.shared.global [%0], [%1], 16;" :: "r"(dst), "l"(src));
}
__device__ __forceinline__ void cpcommit() { asm volatile("cp.async.commit_group;"); }
__device__ __forceinline__ void cpwait0()  { asm volatile("cp.async.wait_group 0;"); }

__device__ __forceinline__ void mma16816(float* c, const uint32_t* a, const uint32_t* b) {
    asm volatile(
        "mma.sync.aligned.m16n8k16.row.col.f32.bf16.bf16.f32 "
        "{%0,%1,%2,%3},{%4,%5,%6,%7},{%8,%9},{%0,%1,%2,%3};"
        : "+f"(c[0]), "+f"(c[1]), "+f"(c[2]), "+f"(c[3])
        : "r"(a[0]), "r"(a[1]), "r"(a[2]), "r"(a[3]), "r"(b[0]), "r"(b[1]));
}
__device__ __forceinline__ uint32_t swoff(int row, int c) {
    return ((uint32_t)row << 8) + (uint32_t)((c ^ (row & 7)) << 4);
}

// ---------------- weight conversion ----------------
__global__ void cvt_all(const float* __restrict__ qw, const float* __restrict__ kvw,
                        const float* __restrict__ pw, const float* __restrict__ f1w,
                        const float* __restrict__ f2w) {
    int i = blockIdx.x * blockDim.x + threadIdx.x;
    if (i < Cc * Cc)     g_qw[i]  = __float2bfloat16(qw[i]);
    if (i < 2 * Cc * Cc) g_kvw[i] = __float2bfloat16(kvw[i]);
    if (i < Cc * Cc)     g_pw[i]  = __float2bfloat16(pw[i]);
    if (i < MLPH * Cc)   g_f1w[i] = __float2bfloat16(f1w[i]);
    if (i < Cc * MLPH)   g_f2w[i] = __float2bfloat16(f2w[i]);
}

// ---------------- warp-per-token LayerNorm (LN1 only) ----------------
__device__ __forceinline__ void warp_red2(float& s, float& q) {
#pragma unroll
    for (int o = 16; o; o >>= 1) {
        s += __shfl_xor_sync(0xffffffffu, s, o);
        q += __shfl_xor_sync(0xffffffffu, q, o);
    }
}
__device__ __forceinline__ void ln_one(const float* __restrict__ src,
                                       const float* __restrict__ gamma,
                                       const float* __restrict__ beta,
                                       __nv_bfloat16* __restrict__ dst,
                                       int t, int wt, int lane) {
    float4 xv = ((const float4*)(src + (size_t)t * Cc))[lane];
    float s = xv.x + xv.y + xv.z + xv.w;
    float q = xv.x * xv.x + xv.y * xv.y + xv.z * xv.z + xv.w * xv.w;
    warp_red2(s, q);
    float mu = s * (1.0f / Cc);
    float var = q * (1.0f / Cc) - mu * mu;
    float r = rsqrtf(var + EPS);
    float4 g = ((const float4*)gamma)[lane];
    float4 b = ((const float4*)beta)[lane];
    __nv_bfloat162 p0 = {__float2bfloat16((xv.x - mu) * r * g.x + b.x),
                         __float2bfloat16((xv.y - mu) * r * g.y + b.y)};
    __nv_bfloat162 p1 = {__float2bfloat16((xv.z - mu) * r * g.z + b.z),
                         __float2bfloat16((xv.w - mu) * r * g.w + b.w)};
    uint2 out;
    out.x = *(uint32_t*)&p0;
    out.y = *(uint32_t*)&p1;
    *(uint2*)(dst + (size_t)wt * Cc + lane * 4) = out;
}

__global__ void __launch_bounds__(256) ln1_kernel(
    const float* __restrict__ x, const float* __restrict__ v,
    const float* __restrict__ g1, const float* __restrict__ b1,
    const float* __restrict__ gv, const float* __restrict__ bv) {
    int warp = threadIdx.x >> 5, lane = threadIdx.x & 31;
    int t = blockIdx.x * 8 + warp;
    int b = t / L, l = t - b * L;
    int row = l / Wdim, col = l - row * Wdim;
    int wy = row / WS, iy = row - wy * WS;
    int wx = col / WS, ix = col - wx * WS;
    int wt = ((b * WPB) + wy * 16 + wx) * NTOK + iy * WS + ix;
    ln_one(x, g1, b1, g_xn, t, wt, lane);
    ln_one(v, gv, bv, g_vn, t, wt, lane);
}

// ---------------- M-looped GEMM, NTILES weight tiles resident, A double-buffered ----------------
// EPI: 0=Q  1=KV  3=FC1(gelu)
template <int MT, int NTILES, int EPI>
__global__ void __launch_bounds__(256, 2) gemm_ml(const float* __restrict__ bias,
                                                  const float* __restrict__ res) {
    extern __shared__ __nv_bfloat16 sm[];
    const uint32_t sA_u[2] = {s2u(sm), s2u(sm) + 32768};
    const uint32_t sB_u = s2u(sm) + 65536;   // NTILES x 16KB

    const __nv_bfloat16* A = (EPI == 0) ? g_xn : (EPI == 1) ? g_vn : g_xon;
    const __nv_bfloat16* W = (EPI == 0) ? g_qw : (EPI == 1) ? g_kvw : g_f1w;

    const int tid = threadIdx.x, warp = tid >> 5, lane = tid & 31;
    const int mbase = blockIdx.x * (128 * MT);
    const int n0 = blockIdx.y * (64 * NTILES);
    const int wm = (warp & 3) * 32, wn = (warp >> 2) * 32;
    const int g = lane >> 2, tg = lane & 3;
    const int a_row = wm + (lane & 15), a_ch = lane >> 4;
    const int b_row = wn + ((lane >> 4) << 3) + (lane & 7), b_ch = (lane >> 3) & 1;

    float breg[NTILES][8];
#pragma unroll
    for (int nt = 0; nt < NTILES; nt++)
#pragma unroll
        for (int ni = 0; ni < 4; ni++)
#pragma unroll
            for (int cc = 0; cc < 2; cc++)
                breg[nt][ni * 2 + cc] =
                    __ldg(bias + n0 + nt * 64 + wn + ni * 8 + tg * 2 + cc);

#pragma unroll
    for (int i = 0; i < 4 * NTILES; i++) {
        int idx = tid + i * 256;
        int bt = idx >> 10, rem = idx & 1023;
        int row = rem >> 4, c = rem & 15;
        cpasync16(sB_u + bt * 16384 + swoff(row, c),
                  W + (size_t)(n0 + bt * 64 + row) * Cc + c * 8);
    }
#pragma unroll
    for (int i = 0; i < 8; i++) {
        int idx = tid + i * 256;
        int row = idx >> 4, c = idx & 15;
        cpasync16(sA_u[0] + swoff(row, c), A + (size_t)(mbase + row) * Cc + c * 8);
    }
    cpcommit();

    for (int mt = 0; mt < MT; mt++) {
        cpwait0();
        __syncthreads();
        if (mt + 1 < MT) {
            const int mn = mbase + (mt + 1) * 128;
#pragma unroll
            for (int i = 0; i < 8; i++) {
                int idx = tid + i * 256;
                int row = idx >> 4, c = idx & 15;
                cpasync16(sA_u[(mt + 1) & 1] + swoff(row, c),
                          A + (size_t)(mn + row) * Cc + c * 8);
            }
            cpcommit();
        }
        const uint32_t sAc = sA_u[mt & 1];
        const int m0 = mbase + mt * 128;

#pragma unroll
        for (int nt = 0; nt < NTILES; nt++) {
            const uint32_t sBc = sB_u + nt * 16384;
            const int nc0 = n0 + nt * 64;

            float acc[2][4][4];
#pragma unroll
            for (int a = 0; a < 2; a++)
#pragma unroll
                for (int b = 0; b < 4; b++)
#pragma unroll
                    for (int c = 0; c < 4; c++) acc[a][b][c] = 0.0f;

#pragma unroll
            for (int kh = 0; kh < 8; kh++) {
                uint32_t a[2][4];
#pragma unroll
                for (int mi = 0; mi < 2; mi++) {
                    int row = a_row + mi * 16;
                    int ch = (2 * kh + a_ch) ^ (row & 7);
                    ldsm4(a[mi][0], a[mi][1], a[mi][2], a[mi][3],
                          sAc + ((uint32_t)row << 8) + (uint32_t)(ch << 4));
                }
                uint32_t b[2][4];
#pragma unroll
                for (int nj = 0; nj < 2; nj++) {
                    int row = b_row + nj * 16;
                    int ch = (2 * kh + b_ch) ^ (row & 7);
                    ldsm4(b[nj][0], b[nj][1], b[nj][2], b[nj][3],
                          sBc + ((uint32_t)row << 8) + (uint32_t)(ch << 4));
                }
#pragma unroll
                for (int mi = 0; mi < 2; mi++)
#pragma unroll
                    for (int ni = 0; ni < 4; ni++) {
                        uint32_t bb[2] = {b[ni >> 1][(ni & 1) * 2],
                                          b[ni >> 1][(ni & 1) * 2 + 1]};
                        mma16816(acc[mi][ni], a[mi], bb);
                    }
            }

#pragma unroll
            for (int mi = 0; mi < 2; mi++)
#pragma unroll
                for (int rr = 0; rr < 2; rr++) {
                    int row = m0 + wm + mi * 16 + g + rr * 8;
                    if (EPI == 0) {
#pragma unroll
                        for (int ni = 0; ni < 4; ni++) {
                            float v0 = (acc[mi][ni][rr * 2] + breg[nt][ni * 2]) * SCALE;
                            float v1 = (acc[mi][ni][rr * 2 + 1] + breg[nt][ni * 2 + 1]) * SCALE;
                            __nv_bfloat162 p = __float22bfloat162_rn(make_float2(v0, v1));
                            *(uint32_t*)(g_q + (size_t)row * Cc + nc0 + wn + ni * 8 + tg * 2) =
                                *(uint32_t*)&p;
                        }
                    } else if (EPI == 1) {
                        __nv_bfloat16* dst = (nc0 < Cc) ? g_k : g_v;
                        const int nb = (nc0 < Cc) ? nc0 : nc0 - Cc;
#pragma unroll
                        for (int ni = 0; ni < 4; ni++) {
                            float v0 = acc[mi][ni][rr * 2] + breg[nt][ni * 2];
                            float v1 = acc[mi][ni][rr * 2 + 1] + breg[nt][ni * 2 + 1];
                            __nv_bfloat162 p = __float22bfloat162_rn(make_float2(v0, v1));
                            *(uint32_t*)(dst + (size_t)row * Cc + nb + wn + ni * 8 + tg * 2) =
                                *(uint32_t*)&p;
                        }
                    } else {
#pragma unroll
                        for (int ni = 0; ni < 4; ni++) {
                            float v0 = acc[mi][ni][rr * 2] + breg[nt][ni * 2];
                            float v1 = acc[mi][ni][rr * 2 + 1] + breg[nt][ni * 2 + 1];
                            v0 = 0.5f * v0 * (1.0f + erff(v0 * 0.70710678118654752f));
                            v1 = 0.5f * v1 * (1.0f + erff(v1 * 0.70710678118654752f));
                            __nv_bfloat162 p = __float22bfloat162_rn(make_float2(v0, v1));
                            *(uint32_t*)(g_h1 + (size_t)row * MLPH + nc0 + wn + ni * 8 + tg * 2) =
                                *(uint32_t*)&p;
                        }
                    }
                }
        }
    }
}

// ---------------- proj + residual + LN2 fused ----------------
// NTILES=2, y=1: each CTA owns full 128-col rows, so LN2 reduces in-CTA.
__global__ void __launch_bounds__(256, 2) proj_ln(const float* __restrict__ bias,
                                                  const float* __restrict__ res,
                                                  const float* __restrict__ g2,
                                                  const float* __restrict__ b2) {
    constexpr int MT = 4;
    extern __shared__ __nv_bfloat16 sm[];
    const uint32_t sA_u[2] = {s2u(sm), s2u(sm) + 32768};
    const uint32_t sB_u = s2u(sm) + 65536;           // 2 x 16KB
    float2* red  = (float2*)(sm + 49152);            // [128][8] = 8KB
    float2* mur  = (float2*)((char*)red + 8192);     // [128]    = 1KB
    float* sg2   = (float*)((char*)mur + 1024);      // 512B
    float* sb2   = sg2 + 128;                        // 512B

    const int tid = threadIdx.x, warp = tid >> 5, lane = tid & 31;
    const int mbase = blockIdx.x * (128 * MT);
    const int wm = (warp & 3) * 32, wn = (warp >> 2) * 32;
    const int g = lane >> 2, tg = lane & 3;
    const int a_row = wm + (lane & 15), a_ch = lane >> 4;
    const int b_row = wn + ((lane >> 4) << 3) + (lane & 7), b_ch = (lane >> 3) & 1;
    const int slot = (warp >> 2) * 4 + tg;           // 0..7 per row

    float breg[2][8];
#pragma unroll
    for (int nt = 0; nt < 2; nt++)
#pragma unroll
        for (int ni = 0; ni < 4; ni++)
#pragma unroll
            for (int cc = 0; cc < 2; cc++)
                breg[nt][ni * 2 + cc] =
                    __ldg(bias + nt * 64 + wn + ni * 8 + tg * 2 + cc);
    if (tid < 128) { sg2[tid] = g2[tid]; sb2[tid] = b2[tid]; }

#pragma unroll
    for (int i = 0; i < 8; i++) {
        int idx = tid + i * 256;
        int bt = idx >> 10, rem = idx & 1023;
        int row = rem >> 4, c = rem & 15;
        cpasync16(sB_u + bt * 16384 + swoff(row, c),
                  g_pw + (size_t)(bt * 64 + row) * Cc + c * 8);
    }
#pragma unroll
    for (int i = 0; i < 8; i++) {
        int idx = tid + i * 256;
        int row = idx >> 4, c = idx & 15;
        cpasync16(sA_u[0] + swoff(row, c), g_ao + (size_t)(mbase + row) * Cc + c * 8);
    }
    cpcommit();

    for (int mt = 0; mt < MT; mt++) {
        cpwait0();
        __syncthreads();
        if (mt + 1 < MT) {
            const int mn = mbase + (mt + 1) * 128;
#pragma unroll
            for (int i = 0; i < 8; i++) {
                int idx = tid + i * 256;
                int row = idx >> 4, c = idx & 15;
                cpasync16(sA_u[(mt + 1) & 1] + swoff(row, c),
                          g_ao + (size_t)(mn + row) * Cc + c * 8);
            }
            cpcommit();
        }
        const uint32_t sAc = sA_u[mt & 1];
        const int m0 = mbase + mt * 128;

        // scatter rows for this m-tile
        int trow_c[4];
#pragma unroll
        for (int mi = 0; mi < 2; mi++)
#pragma unroll
            for (int rr = 0; rr < 2; rr++) {
                int row = m0 + wm + mi * 16 + g + rr * 8;
                int win = row / NTOK, n = row - win * NTOK;
                int b = win >> 8, wr = win & 255;
                int wy = wr >> 4, wx = wr & 15;
                int iy = n / WS, ix = n - iy * WS;
                trow_c[mi * 2 + rr] = b * L + (wy * WS + iy) * Wdim + wx * WS + ix;
            }

        float psum[4], psq[4];
#pragma unroll
        for (int i = 0; i < 4; i++) { psum[i] = 0.0f; psq[i] = 0.0f; }

#pragma unroll
        for (int nt = 0; nt < 2; nt++) {
            const uint32_t sBc = sB_u + nt * 16384;
            const int nc0 = nt * 64;

            float acc[2][4][4];
#pragma unroll
            for (int a = 0; a < 2; a++)
#pragma unroll
                for (int b = 0; b < 4; b++)
#pragma unroll
                    for (int c = 0; c < 4; c++) acc[a][b][c] = 0.0f;

#pragma unroll
            for (int kh = 0; kh < 8; kh++) {
                uint32_t a[2][4];
#pragma unroll
                for (int mi = 0; mi < 2; mi++) {
                    int row = a_row + mi * 16;
                    int ch = (2 * kh + a_ch) ^ (row & 7);
                    ldsm4(a[mi][0], a[mi][1], a[mi][2], a[mi][3],
                          sAc + ((uint32_t)row << 8) + (uint32_t)(ch << 4));
                }
                uint32_t b[2][4];
#pragma unroll
                for (int nj = 0; nj < 2; nj++) {
                    int row = b_row + nj * 16;
                    int ch = (2 * kh + b_ch) ^ (row & 7);
                    ldsm4(b[nj][0], b[nj][1], b[nj][2], b[nj][3],
                          sBc + ((uint32_t)row << 8) + (uint32_t)(ch << 4));
                }
#pragma unroll
                for (int mi = 0; mi < 2; mi++)
#pragma unroll
                    for (int ni = 0; ni < 4; ni++) {
                        uint32_t bb[2] = {b[ni >> 1][(ni & 1) * 2],
                                          b[ni >> 1][(ni & 1) * 2 + 1]};
                        mma16816(acc[mi][ni], a[mi], bb);
                    }
            }

            // epilogue: write g_xo + accumulate LN partials
#pragma unroll
            for (int mi = 0; mi < 2; mi++)
#pragma unroll
                for (int rr = 0; rr < 2; rr++) {
                    const int ri = mi * 2 + rr;
#pragma unroll
                    for (int ni = 0; ni < 4; ni++) {
                        size_t oi = (size_t)trow_c[ri] * Cc + nc0 + wn + ni * 8 + tg * 2;
                        float2 rv = *(const float2*)(res + oi);
                        float2 ov;
                        ov.x = acc[mi][ni][rr * 2] + breg[nt][ni * 2] + rv.x;
                        ov.y = acc[mi][ni][rr * 2 + 1] + breg[nt][ni * 2 + 1] + rv.y;
                        *(float2*)(g_xo + oi) = ov;
                        psum[ri] += ov.x + ov.y;
                        psq[ri]  += ov.x * ov.x + ov.y * ov.y;
                    }
                }
        }

        // ---- LN2 reduction across 8 threads per row ----
#pragma unroll
        for (int ri = 0; ri < 4; ri++) {
            int rloc = wm + (ri >> 1) * 16 + g + (ri & 1) * 8;
            red[rloc * 8 + slot] = make_float2(psum[ri], psq[ri]);
        }
        __syncthreads();
        if (tid < 128) {
            float s = 0.0f, q = 0.0f;
#pragma unroll
            for (int j = 0; j < 8; j++) {
                float2 p = red[tid * 8 + j];
                s += p.x; q += p.y;
            }
            float mu = s * (1.0f / Cc);
            float var = q * (1.0f / Cc) - mu * mu;
            mur[tid] = make_float2(mu, rsqrtf(var + EPS));
        }
        __syncthreads();

        // ---- normalize: re-read xo (L2-hot) and emit g_xon ----
#pragma unroll
        for (int ri = 0; ri < 4; ri++) {
            int rloc = wm + (ri >> 1) * 16 + g + (ri & 1) * 8;
            float2 mr = mur[rloc];
            const size_t tbase = (size_t)trow_c[ri] * Cc;
#pragma unroll
            for (int nt = 0; nt < 2; nt++)
#pragma unroll
                for (int ni = 0; ni < 4; ni++) {
                    int col = nt * 64 + wn + ni * 8 + tg * 2;
                    float2 xv = *(const float2*)(g_xo + tbase + col);
                    float n0 = (xv.x - mr.x) * mr.y * sg2[col] + sb2[col];
                    float n1 = (xv.y - mr.x) * mr.y * sg2[col + 1] + sb2[col + 1];
                    __nv_bfloat162 p = __float22bfloat162_rn(make_float2(n0, n1));
                    *(uint32_t*)(g_xon + tbase + col) = *(uint32_t*)&p;
                }
        }
    }
}

// ---------------- fc2: full weight resident (128KB), single y, A ring ----------------
__global__ void __launch_bounds__(256) gemm_fc2(const float* __restrict__ bias,
                                                float* __restrict__ outf) {
    constexpr int MT = 4;
    extern __shared__ __nv_bfloat16 sm[];
    const uint32_t sA_u[2] = {s2u(sm), s2u(sm) + 32768};
    const uint32_t sB_u = s2u(sm) + 65536;

    const int tid = threadIdx.x, warp = tid >> 5, lane = tid & 31;
    const int mbase = blockIdx.x * (128 * MT);
    const int wm = (warp & 3) * 32, wn = (warp >> 2) * 32;
    const int g = lane >> 2, tg = lane & 3;
    const int a_row = wm + (lane & 15), a_ch = lane >> 4;
    const int b_row = wn + ((lane >> 4) << 3) + (lane & 7), b_ch = (lane >> 3) & 1;

    float breg[2][8];
#pragma unroll
    for (int nt = 0; nt < 2; nt++)
#pragma unroll
        for (int ni = 0; ni < 4; ni++)
#pragma unroll
            for (int cc = 0; cc < 2; cc++)
                breg[nt][ni * 2 + cc] = __ldg(bias + nt * 64 + wn + ni * 8 + tg * 2 + cc);

#pragma unroll
    for (int i = 0; i < 32; i++) {
        int idx = tid + i * 256;
        int bt = idx >> 10, rem = idx & 1023;
        int kc = bt >> 1, nt = bt & 1;
        int row = rem >> 4, c = rem & 15;
        cpasync16(sB_u + bt * 16384 + swoff(row, c),
                  g_f2w + (size_t)(nt * 64 + row) * MLPH + kc * 128 + c * 8);
    }
#pragma unroll
    for (int i = 0; i < 8; i++) {
        int idx = tid + i * 256;
        int row = idx >> 4, c = idx & 15;
        cpasync16(sA_u[0] + swoff(row, c), g_h1 + (size_t)(mbase + row) * MLPH + c * 8);
    }
    cpcommit();

    float acc[2][2][4][4];
    constexpr int NSTEP = MT * 4;
    for (int step = 0; step < NSTEP; step++) {
        const int mt = step >> 2, kc = step & 3;
        cpwait0();
        __syncthreads();
        if (step + 1 < NSTEP) {
            const int nmt = (step + 1) >> 2, nkc = (step + 1) & 3;
            const int mrow = mbase + nmt * 128;
#pragma unroll
            for (int i = 0; i < 8; i++) {
                int idx = tid + i * 256;
                int row = idx >> 4, c = idx & 15;
                cpasync16(sA_u[(step + 1) & 1] + swoff(row, c),
                          g_h1 + (size_t)(mrow + row) * MLPH + nkc * 128 + c * 8);
            }
            cpcommit();
        }
        if (kc == 0) {
#pragma unroll
            for (int t = 0; t < 2; t++)
#pragma unroll
                for (int a = 0; a < 2; a++)
#pragma unroll
                    for (int b = 0; b < 4; b++)
#pragma unroll
                        for (int c = 0; c < 4; c++) acc[t][a][b][c] = 0.0f;
        }
        const uint32_t sAc = sA_u[step & 1];

#pragma unroll
        for (int kh = 0; kh < 8; kh++) {
            uint32_t a[2][4];
#pragma unroll
            for (int mi = 0; mi < 2; mi++) {
                int row = a_row + mi * 16;
                int ch = (2 * kh + a_ch) ^ (row & 7);
                ldsm4(a[mi][0], a[mi][1], a[mi][2], a[mi][3],
                      sAc + ((uint32_t)row << 8) + (uint32_t)(ch << 4));
            }
#pragma unroll
            for (int nt = 0; nt < 2; nt++) {
                const uint32_t sBc = sB_u + (kc * 2 + nt) * 16384;
                uint32_t b[2][4];
#pragma unroll
                for (int nj = 0; nj < 2; nj++) {
                    int row = b_row + nj * 16;
                    int ch = (2 * kh + b_ch) ^ (row & 7);
                    ldsm4(b[nj][0], b[nj][1], b[nj][2], b[nj][3],
                          sBc + ((uint32_t)row << 8) + (uint32_t)(ch << 4));
                }
#pragma unroll
                for (int mi = 0; mi < 2; mi++)
#pragma unroll
                    for (int ni = 0; ni < 4; ni++) {
                        uint32_t bb[2] = {b[ni >> 1][(ni & 1) * 2],
                                          b[ni >> 1][(ni & 1) * 2 + 1]};
                        mma16816(acc[nt][mi][ni], a[mi], bb);
                    }
            }
        }

        if (kc == 3) {
            const int m0 = mbase + mt * 128;
#pragma unroll
            for (int nt = 0; nt < 2; nt++)
#pragma unroll
                for (int mi = 0; mi < 2; mi++)
#pragma unroll
                    for (int rr = 0; rr < 2; rr++) {
                        int row = m0 + wm + mi * 16 + g + rr * 8;
#pragma unroll
                        for (int ni = 0; ni < 4; ni++) {
                            size_t oi = (size_t)row * Cc + nt * 64 + wn + ni * 8 + tg * 2;
                            float2 xv = *(const float2*)(g_xo + oi);
                            float2 ov;
                            ov.x = acc[nt][mi][ni][rr * 2] + breg[nt][ni * 2] + xv.x;
                            ov.y = acc[nt][mi][ni][rr * 2 + 1] + breg[nt][ni * 2 + 1] + xv.y;
                            *(float2*)(outf + oi) = ov;
                        }
                    }
        }
    }
}

// ---------------- tensor-core windowed attention ----------------
__global__ void __launch_bounds__(128) attn_kernel(const float* __restrict__ rpb) {
    constexpr int SST = 136;
    __shared__ __nv_bfloat16 sK[64 * SST];
    __shared__ __nv_bfloat16 sV[64 * SST];
    __shared__ float sb[HEADS * 169];

    const int win = blockIdx.x;
    const int tid = threadIdx.x, warp = tid >> 5, lane = tid & 31;
    const int g = lane >> 2, tg = lane & 3;
    const size_t base = (size_t)win * NTOK * Cc;

    for (int i = tid; i < 49 * 16; i += 128) {
        int r = i >> 4, cb = (i & 15) * 8;
        *(uint4*)&sK[r * SST + cb] = *(const uint4*)(g_k + base + (size_t)r * Cc + cb);
        *(uint4*)&sV[r * SST + cb] = *(const uint4*)(g_v + base + (size_t)r * Cc + cb);
    }
    for (int i = tid; i < 15 * 16; i += 128) {
        int r = 49 + (i >> 4), cb = (i & 15) * 8;
        *(uint4*)&sV[r * SST + cb] = make_uint4(0, 0, 0, 0);
    }
    for (int i = lane; i < 169; i += 32) sb[warp * 169 + i] = rpb[i * HEADS + warp];
    __syncthreads();

    const int hc = warp * HD;
    const float* sbh = &sb[warp * 169];

    uint32_t kb[7][2][2];
#pragma unroll
    for (int nt = 0; nt < 7; nt++)
#pragma unroll
        for (int kh = 0; kh < 2; kh++) {
            const __nv_bfloat16* p = &sK[(nt * 8 + g) * SST + hc + kh * 16 + tg * 2];
            kb[nt][kh][0] = *(const uint32_t*)p;
            kb[nt][kh][1] = *(const uint32_t*)(p + 8);
        }
    uint32_t vb[4][4][2];
#pragma unroll
    for (int kt = 0; kt < 4; kt++)
#pragma unroll
        for (int nd = 0; nd < 4; nd++) {
            int k0 = kt * 16 + tg * 2;
            int c = hc + nd * 8 + g;
            __nv_bfloat162 b0 = {sV[k0 * SST + c], sV[(k0 + 1) * SST + c]};
            __nv_bfloat162 b1 = {sV[(k0 + 8) * SST + c], sV[(k0 + 9) * SST + c]};
            vb[kt][nd][0] = *(uint32_t*)&b0;
            vb[kt][nd][1] = *(uint32_t*)&b1;
        }

#pragma unroll
    for (int mt = 0; mt < 4; mt++) {
        uint32_t qa[2][4];
        int q0 = win * NTOK + mt * 16 + g;
        int q1 = q0 + 8;
        int q0c = q0 < T ? q0 : T - 1;
        int q1c = q1 < T ? q1 : T - 1;
#pragma unroll
        for (int kh = 0; kh < 2; kh++) {
            const __nv_bfloat16* p0 = g_q + (size_t)q0c * Cc + hc + kh * 16 + tg * 2;
            const __nv_bfloat16* p1 = g_q + (size_t)q1c * Cc + hc + kh * 16 + tg * 2;
            qa[kh][0] = *(const uint32_t*)p0;
            qa[kh][1] = *(const uint32_t*)p1;
            qa[kh][2] = *(const uint32_t*)(p0 + 8);
            qa[kh][3] = *(const uint32_t*)(p1 + 8);
        }

        float s[7][4];
#pragma unroll
        for (int nt = 0; nt < 7; nt++)
#pragma unroll
            for (int c = 0; c < 4; c++) s[nt][c] = 0.0f;
#pragma unroll
        for (int kh = 0; kh < 2; kh++)
#pragma unroll
            for (int nt = 0; nt < 7; nt++) mma16816(s[nt], qa[kh], kb[nt][kh]);

        uint32_t pa[4][4];
#pragma unroll
        for (int rr = 0; rr < 2; rr++) {
            int q = mt * 16 + g + rr * 8;
            int qq = q < NTOK ? q : NTOK - 1;
            int qy = qq / WS, qx = qq - qy * WS;
            float ev[14];
            float mx = -1e30f;
#pragma unroll
            for (int nt = 0; nt < 7; nt++)
#pragma unroll
                for (int cc = 0; cc < 2; cc++) {
                    int key = nt * 8 + tg * 2 + cc;
                    float v = s[nt][rr * 2 + cc];
                    if (key < NTOK) {
                        int ky = key / WS, kx = key - ky * WS;
                        v += sbh[(qy - ky + 6) * 13 + (qx - kx + 6)];
                        mx = fmaxf(mx, v);
                    }
                    ev[nt * 2 + cc] = v;
                }
            mx = fmaxf(mx, __shfl_xor_sync(0xffffffffu, mx, 1));
            mx = fmaxf(mx, __shfl_xor_sync(0xffffffffu, mx, 2));
            float sum = 0.0f;
#pragma unroll
            for (int j = 0; j < 14; j++) {
                int key = (j >> 1) * 8 + tg * 2 + (j & 1);
                float e = (key < NTOK) ? __expf(ev[j] - mx) : 0.0f;
                ev[j] = e;
                sum += e;
            }
            sum += __shfl_xor_sync(0xffffffffu, sum, 1);
            sum += __shfl_xor_sync(0xffffffffu, sum, 2);
            float inv = 1.0f / sum;
#pragma unroll
            for (int kt = 0; kt < 4; kt++) {
                int ntA = 2 * kt, ntB = 2 * kt + 1;
                __nv_bfloat162 pA = __float22bfloat162_rn(
                    make_float2(ev[ntA * 2] * inv, ev[ntA * 2 + 1] * inv));
                pa[kt][rr] = *(uint32_t*)&pA;
                if (ntB < 7) {
                    __nv_bfloat162 pB = __float22bfloat162_rn(
                        make_float2(ev[ntB * 2] * inv, ev[ntB * 2 + 1] * inv));
                    pa[kt][2 + rr] = *(uint32_t*)&pB;
                } else {
                    pa[kt][2 + rr] = 0u;
                }
            }
        }

        float o[4][4];
#pragma unroll
        for (int nd = 0; nd < 4; nd++)
#pragma unroll
            for (int c = 0; c < 4; c++) o[nd][c] = 0.0f;
#pragma unroll
        for (int kt = 0; kt < 4; kt++)
#pragma unroll
            for (int nd = 0; nd < 4; nd++) mma16816(o[nd], pa[kt], vb[kt][nd]);

#pragma unroll
        for (int rr = 0; rr < 2; rr++) {
            int q = mt * 16 + g + rr * 8;
            if (q < NTOK) {
#pragma unroll
                for (int nd = 0; nd < 4; nd++) {
                    __nv_bfloat162 p2 = __float22bfloat162_rn(
                        make_float2(o[nd][rr * 2], o[nd][rr * 2 + 1]));
                    *(uint32_t*)(g_ao + base + (size_t)q * Cc + hc + nd * 8 + tg * 2) =
                        *(uint32_t*)&p2;
                }
            }
        }
    }
}

// ---------------- launch ----------------
extern "C" void kernel_launch(void* const* d_in, const int* in_sizes, int n_in,
                              void* d_out, int out_size) {
    const float* x   = (const float*)d_in[0];
    const float* v   = (const float*)d_in[1];
    const float* n1g = (const float*)d_in[2];
    const float* n1b = (const float*)d_in[3];
    const float* nvg = (const float*)d_in[4];
    const float* nvb = (const float*)d_in[5];
    const float* qw  = (const float*)d_in[6];
    const float* qb  = (const float*)d_in[7];
    const float* kvw = (const float*)d_in[8];
    const float* kvb = (const float*)d_in[9];
    const float* rpb = (const float*)d_in[10];
    const float* pw  = (const float*)d_in[11];
    const float* pb  = (const float*)d_in[12];
    const float* n2g = (const float*)d_in[13];
    const float* n2b = (const float*)d_in[14];
    const float* f1w = (const float*)d_in[15];
    const float* f1b = (const float*)d_in[16];
    const float* f2w = (const float*)d_in[17];
    const float* f2b = (const float*)d_in[18];
    float* out = (float*)d_out;

    constexpr int ML1_SMEM = 80 * 1024;    // NTILES=1
    constexpr int PLN_SMEM = 107 * 1024;   // proj_ln: 96KB tiles + 11KB LN
    constexpr int ML2_SMEM = 96 * 1024;    // NTILES=2
    constexpr int FC2_SMEM = 192 * 1024;
    cudaFuncSetAttribute(gemm_ml<4, 1, 0>, cudaFuncAttributeMaxDynamicSharedMemorySize, ML1_SMEM);
    cudaFuncSetAttribute(gemm_ml<8, 1, 1>, cudaFuncAttributeMaxDynamicSharedMemorySize, ML1_SMEM);
    cudaFuncSetAttribute(gemm_ml<4, 2, 3>, cudaFuncAttributeMaxDynamicSharedMemorySize, ML2_SMEM);
    cudaFuncSetAttribute(proj_ln, cudaFuncAttributeMaxDynamicSharedMemorySize, PLN_SMEM);
    cudaFuncSetAttribute(gemm_fc2, cudaFuncAttributeMaxDynamicSharedMemorySize, FC2_SMEM);

    cvt_all<<<(Cc * MLPH + 255) / 256, 256>>>(qw, kvw, pw, f1w, f2w);
    ln1_kernel<<<T / 8, 256>>>(x, v, n1g, n1b, nvg, nvb);
    gemm_ml<4, 1, 0><<<dim3(T / 512, 2), 256, ML1_SMEM>>>(qb, nullptr);     // q
    gemm_ml<8, 1, 1><<<dim3(T / 1024, 4), 256, ML1_SMEM>>>(kvb, nullptr);   // k,v
    attn_kernel<<<NWIN, 128>>>(rpb);
    proj_ln<<<T / 512, 256, PLN_SMEM>>>(pb, x, n2g, n2b);                   // proj + LN2
    gemm_ml<4, 2, 3><<<dim3(T / 512, 4), 256, ML2_SMEM>>>(f1b, nullptr);    // fc1
    gemm_fc2<<<T / 512, 256, FC2_SMEM>>>(f2b, out);                         // fc2
}

// round 14
// speedup vs baseline: 1.0747x; 1.0747x over previous
#include <cuda_runtime.h>
#include <cuda_bf16.h>
#include <cstdint>

// ---------------- problem constants ----------------
constexpr int Bsz   = 16;
constexpr int Hdim  = 112;
constexpr int Wdim  = 112;
constexpr int Cc    = 128;
constexpr int HEADS = 4;
constexpr int HD    = 32;
constexpr int WS    = 7;
constexpr int L     = Hdim * Wdim;        // 12544
constexpr int T     = Bsz * L;            // 200704
constexpr int NTOK  = WS * WS;            // 49
constexpr int WPB   = (Hdim / WS) * (Wdim / WS);  // 256
constexpr int NWIN  = Bsz * WPB;          // 4096
constexpr int MLPH  = 512;
constexpr int MIT   = 4;
constexpr float SCALE = 0.17677669529663687f;
constexpr float EPS   = 1e-5f;

// ---------------- device scratch ----------------
__device__ __align__(16) __nv_bfloat16 g_xn[T * Cc];
__device__ __align__(16) __nv_bfloat16 g_vn[T * Cc];
__device__ __align__(16) __nv_bfloat16 g_q [T * Cc];
__device__ __align__(16) __nv_bfloat16 g_k [T * Cc];
__device__ __align__(16) __nv_bfloat16 g_v [T * Cc];
__device__ __align__(16) __nv_bfloat16 g_ao[T * Cc];
__device__ __align__(16) float         g_xo[T * Cc];
__device__ __align__(16) __nv_bfloat16 g_xon[T * Cc];
__device__ __align__(16) __nv_bfloat16 g_h1[(size_t)T * MLPH];
__device__ __align__(16) __nv_bfloat16 g_qw [Cc * Cc];
__device__ __align__(16) __nv_bfloat16 g_kvw[2 * Cc * Cc];
__device__ __align__(16) __nv_bfloat16 g_pw [Cc * Cc];
__device__ __align__(16) __nv_bfloat16 g_f1w[MLPH * Cc];
__device__ __align__(16) __nv_bfloat16 g_f2w[Cc * MLPH];

// ---------------- helpers ----------------
__device__ __forceinline__ uint32_t s2u(const void* p) {
    return (uint32_t)__cvta_generic_to_shared(p);
}
__device__ __forceinline__ void ldsm4(uint32_t& r0, uint32_t& r1, uint32_t& r2,
                                      uint32_t& r3, uint32_t addr) {
    asm volatile("ldmatrix.sync.aligned.m8n8.x4.shared.b16 {%0,%1,%2,%3},[%4];"
                 : "=r"(r0), "=r"(r1), "=r"(r2), "=r"(r3) : "r"(addr));
}
__device__ __forceinline__ void cpasync16(uint32_t dst, const void* src) {
    asm volatile("cp.async.cg.shared.global [%0], [%1], 16;" :: "r"(dst), "l"(src));
}
__device__ __forceinline__ void cpcommit() { asm volatile("cp.async.commit_group;"); }
__device__ __forceinline__ void cpwait0()  { asm volatile("cp.async.wait_group 0;"); }

__device__ __forceinline__ void mma16816(float* c, const uint32_t* a, const uint32_t* b) {
    asm volatile(
        "mma.sync.aligned.m16n8k16.row.col.f32.bf16.bf16.f32 "
        "{%0,%1,%2,%3},{%4,%5,%6,%7},{%8,%9},{%0,%1,%2,%3};"
        : "+f"(c[0]), "+f"(c[1]), "+f"(c[2]), "+f"(c[3])
        : "r"(a[0]), "r"(a[1]), "r"(a[2]), "r"(a[3]), "r"(b[0]), "r"(b[1]));
}
__device__ __forceinline__ uint32_t swoff(int row, int c) {
    return ((uint32_t)row << 8) + (uint32_t)((c ^ (row & 7)) << 4);
}

// ---------------- weight conversion ----------------
__global__ void cvt_all(const float* __restrict__ qw, const float* __restrict__ kvw,
                        const float* __restrict__ pw, const float* __restrict__ f1w,
                        const float* __restrict__ f2w) {
    int i = blockIdx.x * blockDim.x + threadIdx.x;
    if (i < Cc * Cc)     g_qw[i]  = __float2bfloat16(qw[i]);
    if (i < 2 * Cc * Cc) g_kvw[i] = __float2bfloat16(kvw[i]);
    if (i < Cc * Cc)     g_pw[i]  = __float2bfloat16(pw[i]);
    if (i < MLPH * Cc)   g_f1w[i] = __float2bfloat16(f1w[i]);
    if (i < Cc * MLPH)   g_f2w[i] = __float2bfloat16(f2w[i]);
}

// ---------------- LayerNorm: interleaved-chain versions ----------------
__device__ __forceinline__ void ln_finish(const float4& xv, float s, float q,
                                          const float4& g, const float4& b,
                                          __nv_bfloat16* dst, size_t off) {
    float mu = s * (1.0f / Cc);
    float var = q * (1.0f / Cc) - mu * mu;
    float r = rsqrtf(var + EPS);
    __nv_bfloat162 p0 = {__float2bfloat16((xv.x - mu) * r * g.x + b.x),
                         __float2bfloat16((xv.y - mu) * r * g.y + b.y)};
    __nv_bfloat162 p1 = {__float2bfloat16((xv.z - mu) * r * g.z + b.z),
                         __float2bfloat16((xv.w - mu) * r * g.w + b.w)};
    uint2 out;
    out.x = *(uint32_t*)&p0;
    out.y = *(uint32_t*)&p1;
    *(uint2*)(dst + off) = out;
}

// ln1: x,v loads issued together; 4 interleaved shuffle chains
__global__ void __launch_bounds__(256) ln1_kernel(
    const float* __restrict__ x, const float* __restrict__ v,
    const float* __restrict__ g1, const float* __restrict__ b1,
    const float* __restrict__ gv, const float* __restrict__ bv) {
    int warp = threadIdx.x >> 5, lane = threadIdx.x & 31;
    int t = blockIdx.x * 8 + warp;
    int b = t / L, l = t - b * L;
    int row = l / Wdim, col = l - row * Wdim;
    int wy = row / WS, iy = row - wy * WS;
    int wx = col / WS, ix = col - wx * WS;
    int wt = ((b * WPB) + wy * 16 + wx) * NTOK + iy * WS + ix;

    float4 xv = ((const float4*)(x + (size_t)t * Cc))[lane];
    float4 vv = ((const float4*)(v + (size_t)t * Cc))[lane];
    float4 gx = ((const float4*)g1)[lane];
    float4 bx = ((const float4*)b1)[lane];
    float4 gvv = ((const float4*)gv)[lane];
    float4 bvv = ((const float4*)bv)[lane];

    float sx = xv.x + xv.y + xv.z + xv.w;
    float qx = xv.x * xv.x + xv.y * xv.y + xv.z * xv.z + xv.w * xv.w;
    float sv = vv.x + vv.y + vv.z + vv.w;
    float qv = vv.x * vv.x + vv.y * vv.y + vv.z * vv.z + vv.w * vv.w;
#pragma unroll
    for (int o = 16; o; o >>= 1) {
        sx += __shfl_xor_sync(0xffffffffu, sx, o);
        qx += __shfl_xor_sync(0xffffffffu, qx, o);
        sv += __shfl_xor_sync(0xffffffffu, sv, o);
        qv += __shfl_xor_sync(0xffffffffu, qv, o);
    }
    size_t off = (size_t)wt * Cc + lane * 4;
    ln_finish(xv, sx, qx, gx, bx, g_xn, off);
    ln_finish(vv, sv, qv, gvv, bvv, g_vn, off);
}

// ln2: 2 tokens per warp, loads batched
__global__ void __launch_bounds__(256) ln2_kernel(
    const float* __restrict__ g2, const float* __restrict__ b2) {
    int warp = threadIdx.x >> 5, lane = threadIdx.x & 31;
    int t0 = blockIdx.x * 16 + warp * 2;

    float4 a = ((const float4*)(g_xo + (size_t)t0 * Cc))[lane];
    float4 c = ((const float4*)(g_xo + (size_t)(t0 + 1) * Cc))[lane];
    float4 g = ((const float4*)g2)[lane];
    float4 b = ((const float4*)b2)[lane];

    float sa = a.x + a.y + a.z + a.w;
    float qa = a.x * a.x + a.y * a.y + a.z * a.z + a.w * a.w;
    float sc = c.x + c.y + c.z + c.w;
    float qc = c.x * c.x + c.y * c.y + c.z * c.z + c.w * c.w;
#pragma unroll
    for (int o = 16; o; o >>= 1) {
        sa += __shfl_xor_sync(0xffffffffu, sa, o);
        qa += __shfl_xor_sync(0xffffffffu, qa, o);
        sc += __shfl_xor_sync(0xffffffffu, sc, o);
        qc += __shfl_xor_sync(0xffffffffu, qc, o);
    }
    ln_finish(a, sa, qa, g, b, g_xon, (size_t)t0 * Cc + lane * 4);
    ln_finish(c, sc, qc, g, b, g_xon, (size_t)(t0 + 1) * Cc + lane * 4);
}

// ---------------- M-looped GEMM, NTILES weight tiles resident, A double-buffered ----------------
// EPI: 0=Q  1=KV  2=PROJ(+x, scatter)  3=FC1(gelu)
template <int NTILES, int EPI>
__global__ void __launch_bounds__(256, 2) gemm_ml(const float* __restrict__ bias,
                                                  const float* __restrict__ res) {
    extern __shared__ __nv_bfloat16 sm[];
    const uint32_t sA_u[2] = {s2u(sm), s2u(sm) + 32768};
    const uint32_t sB_u = s2u(sm) + 65536;

    const __nv_bfloat16* A =
        (EPI == 0) ? g_xn : (EPI == 1) ? g_vn : (EPI == 2) ? g_ao : g_xon;
    const __nv_bfloat16* W =
        (EPI == 0) ? g_qw : (EPI == 1) ? g_kvw : (EPI == 2) ? g_pw : g_f1w;

    const int tid = threadIdx.x, warp = tid >> 5, lane = tid & 31;
    const int mbase = blockIdx.x * (128 * MIT);
    const int n0 = blockIdx.y * (64 * NTILES);
    const int wm = (warp & 3) * 32, wn = (warp >> 2) * 32;
    const int g = lane >> 2, tg = lane & 3;
    const int a_row = wm + (lane & 15), a_ch = lane >> 4;
    const int b_row = wn + ((lane >> 4) << 3) + (lane & 7), b_ch = (lane >> 3) & 1;

    float breg[NTILES][8];
#pragma unroll
    for (int nt = 0; nt < NTILES; nt++)
#pragma unroll
        for (int ni = 0; ni < 4; ni++)
#pragma unroll
            for (int cc = 0; cc < 2; cc++)
                breg[nt][ni * 2 + cc] =
                    __ldg(bias + n0 + nt * 64 + wn + ni * 8 + tg * 2 + cc);

#pragma unroll
    for (int i = 0; i < 4 * NTILES; i++) {
        int idx = tid + i * 256;
        int bt = idx >> 10, rem = idx & 1023;
        int row = rem >> 4, c = rem & 15;
        cpasync16(sB_u + bt * 16384 + swoff(row, c),
                  W + (size_t)(n0 + bt * 64 + row) * Cc + c * 8);
    }
#pragma unroll
    for (int i = 0; i < 8; i++) {
        int idx = tid + i * 256;
        int row = idx >> 4, c = idx & 15;
        cpasync16(sA_u[0] + swoff(row, c), A + (size_t)(mbase + row) * Cc + c * 8);
    }
    cpcommit();

    for (int mt = 0; mt < MIT; mt++) {
        cpwait0();
        __syncthreads();
        if (mt + 1 < MIT) {
            const int mn = mbase + (mt + 1) * 128;
#pragma unroll
            for (int i = 0; i < 8; i++) {
                int idx = tid + i * 256;
                int row = idx >> 4, c = idx & 15;
                cpasync16(sA_u[(mt + 1) & 1] + swoff(row, c),
                          A + (size_t)(mn + row) * Cc + c * 8);
            }
            cpcommit();
        }
        const uint32_t sAc = sA_u[mt & 1];
        const int m0 = mbase + mt * 128;

#pragma unroll
        for (int nt = 0; nt < NTILES; nt++) {
            const uint32_t sBc = sB_u + nt * 16384;
            const int nc0 = n0 + nt * 64;

            float acc[2][4][4];
#pragma unroll
            for (int a = 0; a < 2; a++)
#pragma unroll
                for (int b = 0; b < 4; b++)
#pragma unroll
                    for (int c = 0; c < 4; c++) acc[a][b][c] = 0.0f;

#pragma unroll
            for (int kh = 0; kh < 8; kh++) {
                uint32_t a[2][4];
#pragma unroll
                for (int mi = 0; mi < 2; mi++) {
                    int row = a_row + mi * 16;
                    int ch = (2 * kh + a_ch) ^ (row & 7);
                    ldsm4(a[mi][0], a[mi][1], a[mi][2], a[mi][3],
                          sAc + ((uint32_t)row << 8) + (uint32_t)(ch << 4));
                }
                uint32_t b[2][4];
#pragma unroll
                for (int nj = 0; nj < 2; nj++) {
                    int row = b_row + nj * 16;
                    int ch = (2 * kh + b_ch) ^ (row & 7);
                    ldsm4(b[nj][0], b[nj][1], b[nj][2], b[nj][3],
                          sBc + ((uint32_t)row << 8) + (uint32_t)(ch << 4));
                }
#pragma unroll
                for (int mi = 0; mi < 2; mi++)
#pragma unroll
                    for (int ni = 0; ni < 4; ni++) {
                        uint32_t bb[2] = {b[ni >> 1][(ni & 1) * 2],
                                          b[ni >> 1][(ni & 1) * 2 + 1]};
                        mma16816(acc[mi][ni], a[mi], bb);
                    }
            }

#pragma unroll
            for (int mi = 0; mi < 2; mi++)
#pragma unroll
                for (int rr = 0; rr < 2; rr++) {
                    int row = m0 + wm + mi * 16 + g + rr * 8;
                    if (EPI == 0) {
#pragma unroll
                        for (int ni = 0; ni < 4; ni++) {
                            float v0 = (acc[mi][ni][rr * 2] + breg[nt][ni * 2]) * SCALE;
                            float v1 = (acc[mi][ni][rr * 2 + 1] + breg[nt][ni * 2 + 1]) * SCALE;
                            __nv_bfloat162 p = __float22bfloat162_rn(make_float2(v0, v1));
                            *(uint32_t*)(g_q + (size_t)row * Cc + nc0 + wn + ni * 8 + tg * 2) =
                                *(uint32_t*)&p;
                        }
                    } else if (EPI == 1) {
                        __nv_bfloat16* dst = (nc0 < Cc) ? g_k : g_v;
                        const int nb = (nc0 < Cc) ? nc0 : nc0 - Cc;
#pragma unroll
                        for (int ni = 0; ni < 4; ni++) {
                            float v0 = acc[mi][ni][rr * 2] + breg[nt][ni * 2];
                            float v1 = acc[mi][ni][rr * 2 + 1] + breg[nt][ni * 2 + 1];
                            __nv_bfloat162 p = __float22bfloat162_rn(make_float2(v0, v1));
                            *(uint32_t*)(dst + (size_t)row * Cc + nb + wn + ni * 8 + tg * 2) =
                                *(uint32_t*)&p;
                        }
                    } else if (EPI == 2) {
                        int win = row / NTOK, n = row - win * NTOK;
                        int b = win >> 8, wr = win & 255;
                        int wy = wr >> 4, wx = wr & 15;
                        int iy = n / WS, ix = n - iy * WS;
                        int trow = b * L + (wy * WS + iy) * Wdim + wx * WS + ix;
#pragma unroll
                        for (int ni = 0; ni < 4; ni++) {
                            size_t oi = (size_t)trow * Cc + nc0 + wn + ni * 8 + tg * 2;
                            float2 rv = *(const float2*)(res + oi);
                            float2 ov;
                            ov.x = acc[mi][ni][rr * 2] + breg[nt][ni * 2] + rv.x;
                            ov.y = acc[mi][ni][rr * 2 + 1] + breg[nt][ni * 2 + 1] + rv.y;
                            *(float2*)(g_xo + oi) = ov;
                        }
                    } else {
#pragma unroll
                        for (int ni = 0; ni < 4; ni++) {
                            float v0 = acc[mi][ni][rr * 2] + breg[nt][ni * 2];
                            float v1 = acc[mi][ni][rr * 2 + 1] + breg[nt][ni * 2 + 1];
                            v0 = 0.5f * v0 * (1.0f + erff(v0 * 0.70710678118654752f));
                            v1 = 0.5f * v1 * (1.0f + erff(v1 * 0.70710678118654752f));
                            __nv_bfloat162 p = __float22bfloat162_rn(make_float2(v0, v1));
                            *(uint32_t*)(g_h1 + (size_t)row * MLPH + nc0 + wn + ni * 8 + tg * 2) =
                                *(uint32_t*)&p;
                        }
                    }
                }
        }
    }
}

// ---------------- fc2: full weight resident (128KB), single y, A ring ----------------
__global__ void __launch_bounds__(256) gemm_fc2(const float* __restrict__ bias,
                                                float* __restrict__ outf) {
    extern __shared__ __nv_bfloat16 sm[];
    const uint32_t sA_u[2] = {s2u(sm), s2u(sm) + 32768};
    const uint32_t sB_u = s2u(sm) + 65536;

    const int tid = threadIdx.x, warp = tid >> 5, lane = tid & 31;
    const int mbase = blockIdx.x * (128 * MIT);
    const int wm = (warp & 3) * 32, wn = (warp >> 2) * 32;
    const int g = lane >> 2, tg = lane & 3;
    const int a_row = wm + (lane & 15), a_ch = lane >> 4;
    const int b_row = wn + ((lane >> 4) << 3) + (lane & 7), b_ch = (lane >> 3) & 1;

    float breg[2][8];
#pragma unroll
    for (int nt = 0; nt < 2; nt++)
#pragma unroll
        for (int ni = 0; ni < 4; ni++)
#pragma unroll
            for (int cc = 0; cc < 2; cc++)
                breg[nt][ni * 2 + cc] = __ldg(bias + nt * 64 + wn + ni * 8 + tg * 2 + cc);

#pragma unroll
    for (int i = 0; i < 32; i++) {
        int idx = tid + i * 256;
        int bt = idx >> 10, rem = idx & 1023;
        int kc = bt >> 1, nt = bt & 1;
        int row = rem >> 4, c = rem & 15;
        cpasync16(sB_u + bt * 16384 + swoff(row, c),
                  g_f2w + (size_t)(nt * 64 + row) * MLPH + kc * 128 + c * 8);
    }
#pragma unroll
    for (int i = 0; i < 8; i++) {
        int idx = tid + i * 256;
        int row = idx >> 4, c = idx & 15;
        cpasync16(sA_u[0] + swoff(row, c), g_h1 + (size_t)(mbase + row) * MLPH + c * 8);
    }
    cpcommit();

    float acc[2][2][4][4];
    constexpr int NSTEP = MIT * 4;
    for (int step = 0; step < NSTEP; step++) {
        const int mt = step >> 2, kc = step & 3;
        cpwait0();
        __syncthreads();
        if (step + 1 < NSTEP) {
            const int nmt = (step + 1) >> 2, nkc = (step + 1) & 3;
            const int mrow = mbase + nmt * 128;
#pragma unroll
            for (int i = 0; i < 8; i++) {
                int idx = tid + i * 256;
                int row = idx >> 4, c = idx & 15;
                cpasync16(sA_u[(step + 1) & 1] + swoff(row, c),
                          g_h1 + (size_t)(mrow + row) * MLPH + nkc * 128 + c * 8);
            }
            cpcommit();
        }
        if (kc == 0) {
#pragma unroll
            for (int t = 0; t < 2; t++)
#pragma unroll
                for (int a = 0; a < 2; a++)
#pragma unroll
                    for (int b = 0; b < 4; b++)
#pragma unroll
                        for (int c = 0; c < 4; c++) acc[t][a][b][c] = 0.0f;
        }
        const uint32_t sAc = sA_u[step & 1];

#pragma unroll
        for (int kh = 0; kh < 8; kh++) {
            uint32_t a[2][4];
#pragma unroll
            for (int mi = 0; mi < 2; mi++) {
                int row = a_row + mi * 16;
                int ch = (2 * kh + a_ch) ^ (row & 7);
                ldsm4(a[mi][0], a[mi][1], a[mi][2], a[mi][3],
                      sAc + ((uint32_t)row << 8) + (uint32_t)(ch << 4));
            }
#pragma unroll
            for (int nt = 0; nt < 2; nt++) {
                const uint32_t sBc = sB_u + (kc * 2 + nt) * 16384;
                uint32_t b[2][4];
#pragma unroll
                for (int nj = 0; nj < 2; nj++) {
                    int row = b_row + nj * 16;
                    int ch = (2 * kh + b_ch) ^ (row & 7);
                    ldsm4(b[nj][0], b[nj][1], b[nj][2], b[nj][3],
                          sBc + ((uint32_t)row << 8) + (uint32_t)(ch << 4));
                }
#pragma unroll
                for (int mi = 0; mi < 2; mi++)
#pragma unroll
                    for (int ni = 0; ni < 4; ni++) {
                        uint32_t bb[2] = {b[ni >> 1][(ni & 1) * 2],
                                          b[ni >> 1][(ni & 1) * 2 + 1]};
                        mma16816(acc[nt][mi][ni], a[mi], bb);
                    }
            }
        }

        if (kc == 3) {
            const int m0 = mbase + mt * 128;
#pragma unroll
            for (int nt = 0; nt < 2; nt++)
#pragma unroll
                for (int mi = 0; mi < 2; mi++)
#pragma unroll
                    for (int rr = 0; rr < 2; rr++) {
                        int row = m0 + wm + mi * 16 + g + rr * 8;
#pragma unroll
                        for (int ni = 0; ni < 4; ni++) {
                            size_t oi = (size_t)row * Cc + nt * 64 + wn + ni * 8 + tg * 2;
                            float2 xv = *(const float2*)(g_xo + oi);
                            float2 ov;
                            ov.x = acc[nt][mi][ni][rr * 2] + breg[nt][ni * 2] + xv.x;
                            ov.y = acc[nt][mi][ni][rr * 2 + 1] + breg[nt][ni * 2 + 1] + xv.y;
                            *(float2*)(outf + oi) = ov;
                        }
                    }
        }
    }
}

// ---------------- tensor-core windowed attention ----------------
__global__ void __launch_bounds__(128) attn_kernel(const float* __restrict__ rpb) {
    constexpr int SST = 136;
    __shared__ __nv_bfloat16 sK[64 * SST];
    __shared__ __nv_bfloat16 sV[64 * SST];
    __shared__ float sb[HEADS * 169];

    const int win = blockIdx.x;
    const int tid = threadIdx.x, warp = tid >> 5, lane = tid & 31;
    const int g = lane >> 2, tg = lane & 3;
    const size_t base = (size_t)win * NTOK * Cc;

    for (int i = tid; i < 49 * 16; i += 128) {
        int r = i >> 4, cb = (i & 15) * 8;
        *(uint4*)&sK[r * SST + cb] = *(const uint4*)(g_k + base + (size_t)r * Cc + cb);
        *(uint4*)&sV[r * SST + cb] = *(const uint4*)(g_v + base + (size_t)r * Cc + cb);
    }
    for (int i = tid; i < 15 * 16; i += 128) {
        int r = 49 + (i >> 4), cb = (i & 15) * 8;
        *(uint4*)&sV[r * SST + cb] = make_uint4(0, 0, 0, 0);
    }
    for (int i = lane; i < 169; i += 32) sb[warp * 169 + i] = rpb[i * HEADS + warp];
    __syncthreads();

    const int hc = warp * HD;
    const float* sbh = &sb[warp * 169];

    uint32_t kb[7][2][2];
#pragma unroll
    for (int nt = 0; nt < 7; nt++)
#pragma unroll
        for (int kh = 0; kh < 2; kh++) {
            const __nv_bfloat16* p = &sK[(nt * 8 + g) * SST + hc + kh * 16 + tg * 2];
            kb[nt][kh][0] = *(const uint32_t*)p;
            kb[nt][kh][1] = *(const uint32_t*)(p + 8);
        }
    uint32_t vb[4][4][2];
#pragma unroll
    for (int kt = 0; kt < 4; kt++)
#pragma unroll
        for (int nd = 0; nd < 4; nd++) {
            int k0 = kt * 16 + tg * 2;
            int c = hc + nd * 8 + g;
            __nv_bfloat162 b0 = {sV[k0 * SST + c], sV[(k0 + 1) * SST + c]};
            __nv_bfloat162 b1 = {sV[(k0 + 8) * SST + c], sV[(k0 + 9) * SST + c]};
            vb[kt][nd][0] = *(uint32_t*)&b0;
            vb[kt][nd][1] = *(uint32_t*)&b1;
        }

#pragma unroll
    for (int mt = 0; mt < 4; mt++) {
        uint32_t qa[2][4];
        int q0 = win * NTOK + mt * 16 + g;
        int q1 = q0 + 8;
        int q0c = q0 < T ? q0 : T - 1;
        int q1c = q1 < T ? q1 : T - 1;
#pragma unroll
        for (int kh = 0; kh < 2; kh++) {
            const __nv_bfloat16* p0 = g_q + (size_t)q0c * Cc + hc + kh * 16 + tg * 2;
            const __nv_bfloat16* p1 = g_q + (size_t)q1c * Cc + hc + kh * 16 + tg * 2;
            qa[kh][0] = *(const uint32_t*)p0;
            qa[kh][1] = *(const uint32_t*)p1;
            qa[kh][2] = *(const uint32_t*)(p0 + 8);
            qa[kh][3] = *(const uint32_t*)(p1 + 8);
        }

        float s[7][4];
#pragma unroll
        for (int nt = 0; nt < 7; nt++)
#pragma unroll
            for (int c = 0; c < 4; c++) s[nt][c] = 0.0f;
#pragma unroll
        for (int kh = 0; kh < 2; kh++)
#pragma unroll
            for (int nt = 0; nt < 7; nt++) mma16816(s[nt], qa[kh], kb[nt][kh]);

        uint32_t pa[4][4];
#pragma unroll
        for (int rr = 0; rr < 2; rr++) {
            int q = mt * 16 + g + rr * 8;
            int qq = q < NTOK ? q : NTOK - 1;
            int qy = qq / WS, qx = qq - qy * WS;
            float ev[14];
            float mx = -1e30f;
#pragma unroll
            for (int nt = 0; nt < 7; nt++)
#pragma unroll
                for (int cc = 0; cc < 2; cc++) {
                    int key = nt * 8 + tg * 2 + cc;
                    float v = s[nt][rr * 2 + cc];
                    if (key < NTOK) {
                        int ky = key / WS, kx = key - ky * WS;
                        v += sbh[(qy - ky + 6) * 13 + (qx - kx + 6)];
                        mx = fmaxf(mx, v);
                    }
                    ev[nt * 2 + cc] = v;
                }
            mx = fmaxf(mx, __shfl_xor_sync(0xffffffffu, mx, 1));
            mx = fmaxf(mx, __shfl_xor_sync(0xffffffffu, mx, 2));
            float sum = 0.0f;
#pragma unroll
            for (int j = 0; j < 14; j++) {
                int key = (j >> 1) * 8 + tg * 2 + (j & 1);
                float e = (key < NTOK) ? __expf(ev[j] - mx) : 0.0f;
                ev[j] = e;
                sum += e;
            }
            sum += __shfl_xor_sync(0xffffffffu, sum, 1);
            sum += __shfl_xor_sync(0xffffffffu, sum, 2);
            float inv = 1.0f / sum;
#pragma unroll
            for (int kt = 0; kt < 4; kt++) {
                int ntA = 2 * kt, ntB = 2 * kt + 1;
                __nv_bfloat162 pA = __float22bfloat162_rn(
                    make_float2(ev[ntA * 2] * inv, ev[ntA * 2 + 1] * inv));
                pa[kt][rr] = *(uint32_t*)&pA;
                if (ntB < 7) {
                    __nv_bfloat162 pB = __float22bfloat162_rn(
                        make_float2(ev[ntB * 2] * inv, ev[ntB * 2 + 1] * inv));
                    pa[kt][2 + rr] = *(uint32_t*)&pB;
                } else {
                    pa[kt][2 + rr] = 0u;
                }
            }
        }

        float o[4][4];
#pragma unroll
        for (int nd = 0; nd < 4; nd++)
#pragma unroll
            for (int c = 0; c < 4; c++) o[nd][c] = 0.0f;
#pragma unroll
        for (int kt = 0; kt < 4; kt++)
#pragma unroll
            for (int nd = 0; nd < 4; nd++) mma16816(o[nd], pa[kt], vb[kt][nd]);

#pragma unroll
        for (int rr = 0; rr < 2; rr++) {
            int q = mt * 16 + g + rr * 8;
            if (q < NTOK) {
#pragma unroll
                for (int nd = 0; nd < 4; nd++) {
                    __nv_bfloat162 p2 = __float22bfloat162_rn(
                        make_float2(o[nd][rr * 2], o[nd][rr * 2 + 1]));
                    *(uint32_t*)(g_ao + base + (size_t)q * Cc + hc + nd * 8 + tg * 2) =
                        *(uint32_t*)&p2;
                }
            }
        }
    }
}

// ---------------- launch ----------------
extern "C" void kernel_launch(void* const* d_in, const int* in_sizes, int n_in,
                              void* d_out, int out_size) {
    const float* x   = (const float*)d_in[0];
    const float* v   = (const float*)d_in[1];
    const float* n1g = (const float*)d_in[2];
    const float* n1b = (const float*)d_in[3];
    const float* nvg = (const float*)d_in[4];
    const float* nvb = (const float*)d_in[5];
    const float* qw  = (const float*)d_in[6];
    const float* qb  = (const float*)d_in[7];
    const float* kvw = (const float*)d_in[8];
    const float* kvb = (const float*)d_in[9];
    const float* rpb = (const float*)d_in[10];
    const float* pw  = (const float*)d_in[11];
    const float* pb  = (const float*)d_in[12];
    const float* n2g = (const float*)d_in[13];
    const float* n2b = (const float*)d_in[14];
    const float* f1w = (const float*)d_in[15];
    const float* f1b = (const float*)d_in[16];
    const float* f2w = (const float*)d_in[17];
    const float* f2b = (const float*)d_in[18];
    float* out = (float*)d_out;

    constexpr int GX = T / (128 * MIT);          // 392
    constexpr int ML1_SMEM = 80 * 1024;
    constexpr int ML2_SMEM = 96 * 1024;
    constexpr int FC2_SMEM = 192 * 1024;
    cudaFuncSetAttribute(gemm_ml<1, 0>, cudaFuncAttributeMaxDynamicSharedMemorySize, ML1_SMEM);
    cudaFuncSetAttribute(gemm_ml<1, 1>, cudaFuncAttributeMaxDynamicSharedMemorySize, ML1_SMEM);
    cudaFuncSetAttribute(gemm_ml<1, 2>, cudaFuncAttributeMaxDynamicSharedMemorySize, ML1_SMEM);
    cudaFuncSetAttribute(gemm_ml<2, 3>, cudaFuncAttributeMaxDynamicSharedMemorySize, ML2_SMEM);
    cudaFuncSetAttribute(gemm_fc2, cudaFuncAttributeMaxDynamicSharedMemorySize, FC2_SMEM);

    cvt_all<<<(Cc * MLPH + 255) / 256, 256>>>(qw, kvw, pw, f1w, f2w);
    ln1_kernel<<<T / 8, 256>>>(x, v, n1g, n1b, nvg, nvb);
    gemm_ml<1, 0><<<dim3(GX, 2), 256, ML1_SMEM>>>(qb, nullptr);      // q
    gemm_ml<1, 1><<<dim3(GX, 4), 256, ML1_SMEM>>>(kvb, nullptr);     // k,v
    attn_kernel<<<NWIN, 128>>>(rpb);
    gemm_ml<1, 2><<<dim3(GX, 2), 256, ML1_SMEM>>>(pb, x);            // proj + residual
    ln2_kernel<<<T / 16, 256>>>(n2g, n2b);
    gemm_ml<2, 3><<<dim3(GX, 4), 256, ML2_SMEM>>>(f1b, nullptr);     // fc1 + gelu
    gemm_fc2<<<GX, 256, FC2_SMEM>>>(f2b, out);                       // fc2 + residual
}

// round 15
// speedup vs baseline: 1.1162x; 1.0386x over previous
#include <cuda_runtime.h>
#include <cuda_bf16.h>
#include <cstdint>

// ---------------- problem constants ----------------
constexpr int Bsz   = 16;
constexpr int Hdim  = 112;
constexpr int Wdim  = 112;
constexpr int Cc    = 128;
constexpr int HEADS = 4;
constexpr int HD    = 32;
constexpr int WS    = 7;
constexpr int L     = Hdim * Wdim;        // 12544
constexpr int T     = Bsz * L;            // 200704
constexpr int NTOK  = WS * WS;            // 49
constexpr int WPB   = (Hdim / WS) * (Wdim / WS);  // 256
constexpr int NWIN  = Bsz * WPB;          // 4096
constexpr int MLPH  = 512;
constexpr int MIT   = 4;
constexpr float SCALE = 0.17677669529663687f;
constexpr float EPS   = 1e-5f;

// ---------------- device scratch ----------------
__device__ __align__(16) __nv_bfloat16 g_xn[T * Cc];
__device__ __align__(16) __nv_bfloat16 g_vn[T * Cc];
__device__ __align__(16) __nv_bfloat16 g_q [T * Cc];
__device__ __align__(16) __nv_bfloat16 g_k [T * Cc];
__device__ __align__(16) __nv_bfloat16 g_v [T * Cc];
__device__ __align__(16) __nv_bfloat16 g_ao[T * Cc];
__device__ __align__(16) __nv_bfloat16 g_po[T * Cc];     // proj+bias, token order (bf16)
__device__ __align__(16) __nv_bfloat16 g_xon[T * Cc];
__device__ __align__(16) __nv_bfloat16 g_h1[(size_t)T * MLPH];
__device__ __align__(16) __nv_bfloat16 g_qw [Cc * Cc];
__device__ __align__(16) __nv_bfloat16 g_kvw[2 * Cc * Cc];
__device__ __align__(16) __nv_bfloat16 g_pw [Cc * Cc];
__device__ __align__(16) __nv_bfloat16 g_f1w[MLPH * Cc];
__device__ __align__(16) __nv_bfloat16 g_f2w[Cc * MLPH];

// ---------------- helpers ----------------
__device__ __forceinline__ uint32_t s2u(const void* p) {
    return (uint32_t)__cvta_generic_to_shared(p);
}
__device__ __forceinline__ void ldsm4(uint32_t& r0, uint32_t& r1, uint32_t& r2,
                                      uint32_t& r3, uint32_t addr) {
    asm volatile("ldmatrix.sync.aligned.m8n8.x4.shared.b16 {%0,%1,%2,%3},[%4];"
                 : "=r"(r0), "=r"(r1), "=r"(r2), "=r"(r3) : "r"(addr));
}
__device__ __forceinline__ void cpasync16(uint32_t dst, const void* src) {
    asm volatile("cp.async.cg.shared.global [%0], [%1], 16;" :: "r"(dst), "l"(src));
}
__device__ __forceinline__ void cpcommit() { asm volatile("cp.async.commit_group;"); }
__device__ __forceinline__ void cpwait0()  { asm volatile("cp.async.wait_group 0;"); }

__device__ __forceinline__ void mma16816(float* c, const uint32_t* a, const uint32_t* b) {
    asm volatile(
        "mma.sync.aligned.m16n8k16.row.col.f32.bf16.bf16.f32 "
        "{%0,%1,%2,%3},{%4,%5,%6,%7},{%8,%9},{%0,%1,%2,%3};"
        : "+f"(c[0]), "+f"(c[1]), "+f"(c[2]), "+f"(c[3])
        : "r"(a[0]), "r"(a[1]), "r"(a[2]), "r"(a[3]), "r"(b[0]), "r"(b[1]));
}
__device__ __forceinline__ uint32_t swoff(int row, int c) {
    return ((uint32_t)row << 8) + (uint32_t)((c ^ (row & 7)) << 4);
}

// ---------------- weight conversion ----------------
__global__ void cvt_all(const float* __restrict__ qw, const float* __restrict__ kvw,
                        const float* __restrict__ pw, const float* __restrict__ f1w,
                        const float* __restrict__ f2w) {
    int i = blockIdx.x * blockDim.x + threadIdx.x;
    if (i < Cc * Cc)     g_qw[i]  = __float2bfloat16(qw[i]);
    if (i < 2 * Cc * Cc) g_kvw[i] = __float2bfloat16(kvw[i]);
    if (i < Cc * Cc)     g_pw[i]  = __float2bfloat16(pw[i]);
    if (i < MLPH * Cc)   g_f1w[i] = __float2bfloat16(f1w[i]);
    if (i < Cc * MLPH)   g_f2w[i] = __float2bfloat16(f2w[i]);
}

// ---------------- LayerNorm ----------------
__device__ __forceinline__ void ln_finish(const float4& xv, float s, float q,
                                          const float4& g, const float4& b,
                                          __nv_bfloat16* dst, size_t off) {
    float mu = s * (1.0f / Cc);
    float var = q * (1.0f / Cc) - mu * mu;
    float r = rsqrtf(var + EPS);
    __nv_bfloat162 p0 = {__float2bfloat16((xv.x - mu) * r * g.x + b.x),
                         __float2bfloat16((xv.y - mu) * r * g.y + b.y)};
    __nv_bfloat162 p1 = {__float2bfloat16((xv.z - mu) * r * g.z + b.z),
                         __float2bfloat16((xv.w - mu) * r * g.w + b.w)};
    uint2 out;
    out.x = *(uint32_t*)&p0;
    out.y = *(uint32_t*)&p1;
    *(uint2*)(dst + off) = out;
}

__global__ void __launch_bounds__(256) ln1_kernel(
    const float* __restrict__ x, const float* __restrict__ v,
    const float* __restrict__ g1, const float* __restrict__ b1,
    const float* __restrict__ gv, const float* __restrict__ bv) {
    int warp = threadIdx.x >> 5, lane = threadIdx.x & 31;
    int t = blockIdx.x * 8 + warp;
    int b = t / L, l = t - b * L;
    int row = l / Wdim, col = l - row * Wdim;
    int wy = row / WS, iy = row - wy * WS;
    int wx = col / WS, ix = col - wx * WS;
    int wt = ((b * WPB) + wy * 16 + wx) * NTOK + iy * WS + ix;

    float4 xv = ((const float4*)(x + (size_t)t * Cc))[lane];
    float4 vv = ((const float4*)(v + (size_t)t * Cc))[lane];
    float4 gx = ((const float4*)g1)[lane];
    float4 bx = ((const float4*)b1)[lane];
    float4 gvv = ((const float4*)gv)[lane];
    float4 bvv = ((const float4*)bv)[lane];

    float sx = xv.x + xv.y + xv.z + xv.w;
    float qx = xv.x * xv.x + xv.y * xv.y + xv.z * xv.z + xv.w * xv.w;
    float sv = vv.x + vv.y + vv.z + vv.w;
    float qv = vv.x * vv.x + vv.y * vv.y + vv.z * vv.z + vv.w * vv.w;
#pragma unroll
    for (int o = 16; o; o >>= 1) {
        sx += __shfl_xor_sync(0xffffffffu, sx, o);
        qx += __shfl_xor_sync(0xffffffffu, qx, o);
        sv += __shfl_xor_sync(0xffffffffu, sv, o);
        qv += __shfl_xor_sync(0xffffffffu, qv, o);
    }
    size_t off = (size_t)wt * Cc + lane * 4;
    ln_finish(xv, sx, qx, gx, bx, g_xn, off);
    ln_finish(vv, sv, qv, gvv, bvv, g_vn, off);
}

// ln2: xon = LN(x + po)
__global__ void __launch_bounds__(256) ln2_kernel(
    const float* __restrict__ x,
    const float* __restrict__ g2, const float* __restrict__ b2) {
    int warp = threadIdx.x >> 5, lane = threadIdx.x & 31;
    int t = blockIdx.x * 8 + warp;

    float4 a = ((const float4*)(x + (size_t)t * Cc))[lane];
    uint2 pr = *(const uint2*)(g_po + (size_t)t * Cc + lane * 4);
    __nv_bfloat162 p0 = *(__nv_bfloat162*)&pr.x;
    __nv_bfloat162 p1 = *(__nv_bfloat162*)&pr.y;
    a.x += __bfloat162float(p0.x);
    a.y += __bfloat162float(p0.y);
    a.z += __bfloat162float(p1.x);
    a.w += __bfloat162float(p1.y);
    float4 g = ((const float4*)g2)[lane];
    float4 b = ((const float4*)b2)[lane];

    float s = a.x + a.y + a.z + a.w;
    float q = a.x * a.x + a.y * a.y + a.z * a.z + a.w * a.w;
#pragma unroll
    for (int o = 16; o; o >>= 1) {
        s += __shfl_xor_sync(0xffffffffu, s, o);
        q += __shfl_xor_sync(0xffffffffu, q, o);
    }
    ln_finish(a, s, q, g, b, g_xon, (size_t)t * Cc + lane * 4);
}

// ---------------- M-looped GEMM ----------------
// EPI: 2=PROJ(->po bf16, scatter)  3=FC1(gelu)  4=QKV merged (y<2: q, else kv)
template <int NTILES, int EPI>
__global__ void __launch_bounds__(256, 2) gemm_ml(const float* __restrict__ bias,
                                                  const float* __restrict__ bias2) {
    extern __shared__ __nv_bfloat16 sm[];
    const uint32_t sA_u[2] = {s2u(sm), s2u(sm) + 32768};
    const uint32_t sB_u = s2u(sm) + 65536;

    const bool isq = (EPI == 4) && (blockIdx.y < 2);
    const __nv_bfloat16* A =
        (EPI == 2) ? g_ao : (EPI == 3) ? g_xon : (isq ? g_xn : g_vn);
    const __nv_bfloat16* W =
        (EPI == 2) ? g_pw : (EPI == 3) ? g_f1w : (isq ? g_qw : g_kvw);
    const float* bptr = (EPI == 4) ? (isq ? bias : bias2) : bias;

    const int tid = threadIdx.x, warp = tid >> 5, lane = tid & 31;
    const int mbase = blockIdx.x * (128 * MIT);
    const int yb = (EPI == 4) ? (isq ? blockIdx.y : blockIdx.y - 2) : blockIdx.y;
    const int n0 = yb * (64 * NTILES);
    const int wm = (warp & 3) * 32, wn = (warp >> 2) * 32;
    const int g = lane >> 2, tg = lane & 3;
    const int a_row = wm + (lane & 15), a_ch = lane >> 4;
    const int b_row = wn + ((lane >> 4) << 3) + (lane & 7), b_ch = (lane >> 3) & 1;

    float breg[NTILES][8];
#pragma unroll
    for (int nt = 0; nt < NTILES; nt++)
#pragma unroll
        for (int ni = 0; ni < 4; ni++)
#pragma unroll
            for (int cc = 0; cc < 2; cc++)
                breg[nt][ni * 2 + cc] =
                    __ldg(bptr + n0 + nt * 64 + wn + ni * 8 + tg * 2 + cc);

#pragma unroll
    for (int i = 0; i < 4 * NTILES; i++) {
        int idx = tid + i * 256;
        int bt = idx >> 10, rem = idx & 1023;
        int row = rem >> 4, c = rem & 15;
        cpasync16(sB_u + bt * 16384 + swoff(row, c),
                  W + (size_t)(n0 + bt * 64 + row) * Cc + c * 8);
    }
#pragma unroll
    for (int i = 0; i < 8; i++) {
        int idx = tid + i * 256;
        int row = idx >> 4, c = idx & 15;
        cpasync16(sA_u[0] + swoff(row, c), A + (size_t)(mbase + row) * Cc + c * 8);
    }
    cpcommit();

    for (int mt = 0; mt < MIT; mt++) {
        cpwait0();
        __syncthreads();
        if (mt + 1 < MIT) {
            const int mn = mbase + (mt + 1) * 128;
#pragma unroll
            for (int i = 0; i < 8; i++) {
                int idx = tid + i * 256;
                int row = idx >> 4, c = idx & 15;
                cpasync16(sA_u[(mt + 1) & 1] + swoff(row, c),
                          A + (size_t)(mn + row) * Cc + c * 8);
            }
            cpcommit();
        }
        const uint32_t sAc = sA_u[mt & 1];
        const int m0 = mbase + mt * 128;

#pragma unroll
        for (int nt = 0; nt < NTILES; nt++) {
            const uint32_t sBc = sB_u + nt * 16384;
            const int nc0 = n0 + nt * 64;

            float acc[2][4][4];
#pragma unroll
            for (int a = 0; a < 2; a++)
#pragma unroll
                for (int b = 0; b < 4; b++)
#pragma unroll
                    for (int c = 0; c < 4; c++) acc[a][b][c] = 0.0f;

#pragma unroll
            for (int kh = 0; kh < 8; kh++) {
                uint32_t a[2][4];
#pragma unroll
                for (int mi = 0; mi < 2; mi++) {
                    int row = a_row + mi * 16;
                    int ch = (2 * kh + a_ch) ^ (row & 7);
                    ldsm4(a[mi][0], a[mi][1], a[mi][2], a[mi][3],
                          sAc + ((uint32_t)row << 8) + (uint32_t)(ch << 4));
                }
                uint32_t b[2][4];
#pragma unroll
                for (int nj = 0; nj < 2; nj++) {
                    int row = b_row + nj * 16;
                    int ch = (2 * kh + b_ch) ^ (row & 7);
                    ldsm4(b[nj][0], b[nj][1], b[nj][2], b[nj][3],
                          sBc + ((uint32_t)row << 8) + (uint32_t)(ch << 4));
                }
#pragma unroll
                for (int mi = 0; mi < 2; mi++)
#pragma unroll
                    for (int ni = 0; ni < 4; ni++) {
                        uint32_t bb[2] = {b[ni >> 1][(ni & 1) * 2],
                                          b[ni >> 1][(ni & 1) * 2 + 1]};
                        mma16816(acc[mi][ni], a[mi], bb);
                    }
            }

#pragma unroll
            for (int mi = 0; mi < 2; mi++)
#pragma unroll
                for (int rr = 0; rr < 2; rr++) {
                    int row = m0 + wm + mi * 16 + g + rr * 8;
                    if (EPI == 4 && isq) {
#pragma unroll
                        for (int ni = 0; ni < 4; ni++) {
                            float v0 = (acc[mi][ni][rr * 2] + breg[nt][ni * 2]) * SCALE;
                            float v1 = (acc[mi][ni][rr * 2 + 1] + breg[nt][ni * 2 + 1]) * SCALE;
                            __nv_bfloat162 p = __float22bfloat162_rn(make_float2(v0, v1));
                            *(uint32_t*)(g_q + (size_t)row * Cc + nc0 + wn + ni * 8 + tg * 2) =
                                *(uint32_t*)&p;
                        }
                    } else if (EPI == 4) {
                        __nv_bfloat16* dst = (nc0 < Cc) ? g_k : g_v;
                        const int nb = (nc0 < Cc) ? nc0 : nc0 - Cc;
#pragma unroll
                        for (int ni = 0; ni < 4; ni++) {
                            float v0 = acc[mi][ni][rr * 2] + breg[nt][ni * 2];
                            float v1 = acc[mi][ni][rr * 2 + 1] + breg[nt][ni * 2 + 1];
                            __nv_bfloat162 p = __float22bfloat162_rn(make_float2(v0, v1));
                            *(uint32_t*)(dst + (size_t)row * Cc + nb + wn + ni * 8 + tg * 2) =
                                *(uint32_t*)&p;
                        }
                    } else if (EPI == 2) {
                        int win = row / NTOK, n = row - win * NTOK;
                        int b = win >> 8, wr = win & 255;
                        int wy = wr >> 4, wx = wr & 15;
                        int iy = n / WS, ix = n - iy * WS;
                        int trow = b * L + (wy * WS + iy) * Wdim + wx * WS + ix;
#pragma unroll
                        for (int ni = 0; ni < 4; ni++) {
                            float v0 = acc[mi][ni][rr * 2] + breg[nt][ni * 2];
                            float v1 = acc[mi][ni][rr * 2 + 1] + breg[nt][ni * 2 + 1];
                            __nv_bfloat162 p = __float22bfloat162_rn(make_float2(v0, v1));
                            *(uint32_t*)(g_po + (size_t)trow * Cc + nc0 + wn + ni * 8 + tg * 2) =
                                *(uint32_t*)&p;
                        }
                    } else {
#pragma unroll
                        for (int ni = 0; ni < 4; ni++) {
                            float v0 = acc[mi][ni][rr * 2] + breg[nt][ni * 2];
                            float v1 = acc[mi][ni][rr * 2 + 1] + breg[nt][ni * 2 + 1];
                            v0 = 0.5f * v0 * (1.0f + erff(v0 * 0.70710678118654752f));
                            v1 = 0.5f * v1 * (1.0f + erff(v1 * 0.70710678118654752f));
                            __nv_bfloat162 p = __float22bfloat162_rn(make_float2(v0, v1));
                            *(uint32_t*)(g_h1 + (size_t)row * MLPH + nc0 + wn + ni * 8 + tg * 2) =
                                *(uint32_t*)&p;
                        }
                    }
                }
        }
    }
}

// ---------------- fc2: full weight resident, out = acc + b2 + x + po ----------------
__global__ void __launch_bounds__(256) gemm_fc2(const float* __restrict__ bias,
                                                const float* __restrict__ xres,
                                                float* __restrict__ outf) {
    extern __shared__ __nv_bfloat16 sm[];
    const uint32_t sA_u[2] = {s2u(sm), s2u(sm) + 32768};
    const uint32_t sB_u = s2u(sm) + 65536;

    const int tid = threadIdx.x, warp = tid >> 5, lane = tid & 31;
    const int mbase = blockIdx.x * (128 * MIT);
    const int wm = (warp & 3) * 32, wn = (warp >> 2) * 32;
    const int g = lane >> 2, tg = lane & 3;
    const int a_row = wm + (lane & 15), a_ch = lane >> 4;
    const int b_row = wn + ((lane >> 4) << 3) + (lane & 7), b_ch = (lane >> 3) & 1;

    float breg[2][8];
#pragma unroll
    for (int nt = 0; nt < 2; nt++)
#pragma unroll
        for (int ni = 0; ni < 4; ni++)
#pragma unroll
            for (int cc = 0; cc < 2; cc++)
                breg[nt][ni * 2 + cc] = __ldg(bias + nt * 64 + wn + ni * 8 + tg * 2 + cc);

#pragma unroll
    for (int i = 0; i < 32; i++) {
        int idx = tid + i * 256;
        int bt = idx >> 10, rem = idx & 1023;
        int kc = bt >> 1, nt = bt & 1;
        int row = rem >> 4, c = rem & 15;
        cpasync16(sB_u + bt * 16384 + swoff(row, c),
                  g_f2w + (size_t)(nt * 64 + row) * MLPH + kc * 128 + c * 8);
    }
#pragma unroll
    for (int i = 0; i < 8; i++) {
        int idx = tid + i * 256;
        int row = idx >> 4, c = idx & 15;
        cpasync16(sA_u[0] + swoff(row, c), g_h1 + (size_t)(mbase + row) * MLPH + c * 8);
    }
    cpcommit();

    float acc[2][2][4][4];
    constexpr int NSTEP = MIT * 4;
    for (int step = 0; step < NSTEP; step++) {
        const int mt = step >> 2, kc = step & 3;
        cpwait0();
        __syncthreads();
        if (step + 1 < NSTEP) {
            const int nmt = (step + 1) >> 2, nkc = (step + 1) & 3;
            const int mrow = mbase + nmt * 128;
#pragma unroll
            for (int i = 0; i < 8; i++) {
                int idx = tid + i * 256;
                int row = idx >> 4, c = idx & 15;
                cpasync16(sA_u[(step + 1) & 1] + swoff(row, c),
                          g_h1 + (size_t)(mrow + row) * MLPH + nkc * 128 + c * 8);
            }
            cpcommit();
        }
        if (kc == 0) {
#pragma unroll
            for (int t = 0; t < 2; t++)
#pragma unroll
                for (int a = 0; a < 2; a++)
#pragma unroll
                    for (int b = 0; b < 4; b++)
#pragma unroll
                        for (int c = 0; c < 4; c++) acc[t][a][b][c] = 0.0f;
        }
        const uint32_t sAc = sA_u[step & 1];

#pragma unroll
        for (int kh = 0; kh < 8; kh++) {
            uint32_t a[2][4];
#pragma unroll
            for (int mi = 0; mi < 2; mi++) {
                int row = a_row + mi * 16;
                int ch = (2 * kh + a_ch) ^ (row & 7);
                ldsm4(a[mi][0], a[mi][1], a[mi][2], a[mi][3],
                      sAc + ((uint32_t)row << 8) + (uint32_t)(ch << 4));
            }
#pragma unroll
            for (int nt = 0; nt < 2; nt++) {
                const uint32_t sBc = sB_u + (kc * 2 + nt) * 16384;
                uint32_t b[2][4];
#pragma unroll
                for (int nj = 0; nj < 2; nj++) {
                    int row = b_row + nj * 16;
                    int ch = (2 * kh + b_ch) ^ (row & 7);
                    ldsm4(b[nj][0], b[nj][1], b[nj][2], b[nj][3],
                          sBc + ((uint32_t)row << 8) + (uint32_t)(ch << 4));
                }
#pragma unroll
                for (int mi = 0; mi < 2; mi++)
#pragma unroll
                    for (int ni = 0; ni < 4; ni++) {
                        uint32_t bb[2] = {b[ni >> 1][(ni & 1) * 2],
                                          b[ni >> 1][(ni & 1) * 2 + 1]};
                        mma16816(acc[nt][mi][ni], a[mi], bb);
                    }
            }
        }

        if (kc == 3) {
            const int m0 = mbase + mt * 128;
#pragma unroll
            for (int nt = 0; nt < 2; nt++)
#pragma unroll
                for (int mi = 0; mi < 2; mi++)
#pragma unroll
                    for (int rr = 0; rr < 2; rr++) {
                        int row = m0 + wm + mi * 16 + g + rr * 8;
#pragma unroll
                        for (int ni = 0; ni < 4; ni++) {
                            size_t oi = (size_t)row * Cc + nt * 64 + wn + ni * 8 + tg * 2;
                            float2 xv = *(const float2*)(xres + oi);
                            __nv_bfloat162 pv = *(const __nv_bfloat162*)(g_po + oi);
                            float2 ov;
                            ov.x = acc[nt][mi][ni][rr * 2] + breg[nt][ni * 2] + xv.x +
                                   __bfloat162float(pv.x);
                            ov.y = acc[nt][mi][ni][rr * 2 + 1] + breg[nt][ni * 2 + 1] + xv.y +
                                   __bfloat162float(pv.y);
                            *(float2*)(outf + oi) = ov;
                        }
                    }
        }
    }
}

// ---------------- tensor-core windowed attention ----------------
__global__ void __launch_bounds__(128) attn_kernel(const float* __restrict__ rpb) {
    constexpr int SST = 136;
    __shared__ __nv_bfloat16 sK[64 * SST];
    __shared__ __nv_bfloat16 sV[64 * SST];
    __shared__ float sb[HEADS * 169];

    const int win = blockIdx.x;
    const int tid = threadIdx.x, warp = tid >> 5, lane = tid & 31;
    const int g = lane >> 2, tg = lane & 3;
    const size_t base = (size_t)win * NTOK * Cc;

    for (int i = tid; i < 49 * 16; i += 128) {
        int r = i >> 4, cb = (i & 15) * 8;
        *(uint4*)&sK[r * SST + cb] = *(const uint4*)(g_k + base + (size_t)r * Cc + cb);
        *(uint4*)&sV[r * SST + cb] = *(const uint4*)(g_v + base + (size_t)r * Cc + cb);
    }
    for (int i = tid; i < 15 * 16; i += 128) {
        int r = 49 + (i >> 4), cb = (i & 15) * 8;
        *(uint4*)&sV[r * SST + cb] = make_uint4(0, 0, 0, 0);
    }
    for (int i = lane; i < 169; i += 32) sb[warp * 169 + i] = rpb[i * HEADS + warp];
    __syncthreads();

    const int hc = warp * HD;
    const float* sbh = &sb[warp * 169];

    uint32_t kb[7][2][2];
#pragma unroll
    for (int nt = 0; nt < 7; nt++)
#pragma unroll
        for (int kh = 0; kh < 2; kh++) {
            const __nv_bfloat16* p = &sK[(nt * 8 + g) * SST + hc + kh * 16 + tg * 2];
            kb[nt][kh][0] = *(const uint32_t*)p;
            kb[nt][kh][1] = *(const uint32_t*)(p + 8);
        }
    uint32_t vb[4][4][2];
#pragma unroll
    for (int kt = 0; kt < 4; kt++)
#pragma unroll
        for (int nd = 0; nd < 4; nd++) {
            int k0 = kt * 16 + tg * 2;
            int c = hc + nd * 8 + g;
            __nv_bfloat162 b0 = {sV[k0 * SST + c], sV[(k0 + 1) * SST + c]};
            __nv_bfloat162 b1 = {sV[(k0 + 8) * SST + c], sV[(k0 + 9) * SST + c]};
            vb[kt][nd][0] = *(uint32_t*)&b0;
            vb[kt][nd][1] = *(uint32_t*)&b1;
        }

#pragma unroll
    for (int mt = 0; mt < 4; mt++) {
        uint32_t qa[2][4];
        int q0 = win * NTOK + mt * 16 + g;
        int q1 = q0 + 8;
        int q0c = q0 < T ? q0 : T - 1;
        int q1c = q1 < T ? q1 : T - 1;
#pragma unroll
        for (int kh = 0; kh < 2; kh++) {
            const __nv_bfloat16* p0 = g_q + (size_t)q0c * Cc + hc + kh * 16 + tg * 2;
            const __nv_bfloat16* p1 = g_q + (size_t)q1c * Cc + hc + kh * 16 + tg * 2;
            qa[kh][0] = *(const uint32_t*)p0;
            qa[kh][1] = *(const uint32_t*)p1;
            qa[kh][2] = *(const uint32_t*)(p0 + 8);
            qa[kh][3] = *(const uint32_t*)(p1 + 8);
        }

        float s[7][4];
#pragma unroll
        for (int nt = 0; nt < 7; nt++)
#pragma unroll
            for (int c = 0; c < 4; c++) s[nt][c] = 0.0f;
#pragma unroll
        for (int kh = 0; kh < 2; kh++)
#pragma unroll
            for (int nt = 0; nt < 7; nt++) mma16816(s[nt], qa[kh], kb[nt][kh]);

        uint32_t pa[4][4];
#pragma unroll
        for (int rr = 0; rr < 2; rr++) {
            int q = mt * 16 + g + rr * 8;
            int qq = q < NTOK ? q : NTOK - 1;
            int qy = qq / WS, qx = qq - qy * WS;
            float ev[14];
            float mx = -1e30f;
#pragma unroll
            for (int nt = 0; nt < 7; nt++)
#pragma unroll
                for (int cc = 0; cc < 2; cc++) {
                    int key = nt * 8 + tg * 2 + cc;
                    float v = s[nt][rr * 2 + cc];
                    if (key < NTOK) {
                        int ky = key / WS, kx = key - ky * WS;
                        v += sbh[(qy - ky + 6) * 13 + (qx - kx + 6)];
                        mx = fmaxf(mx, v);
                    }
                    ev[nt * 2 + cc] = v;
                }
            mx = fmaxf(mx, __shfl_xor_sync(0xffffffffu, mx, 1));
            mx = fmaxf(mx, __shfl_xor_sync(0xffffffffu, mx, 2));
            float sum = 0.0f;
#pragma unroll
            for (int j = 0; j < 14; j++) {
                int key = (j >> 1) * 8 + tg * 2 + (j & 1);
                float e = (key < NTOK) ? __expf(ev[j] - mx) : 0.0f;
                ev[j] = e;
                sum += e;
            }
            sum += __shfl_xor_sync(0xffffffffu, sum, 1);
            sum += __shfl_xor_sync(0xffffffffu, sum, 2);
            float inv = 1.0f / sum;
#pragma unroll
            for (int kt = 0; kt < 4; kt++) {
                int ntA = 2 * kt, ntB = 2 * kt + 1;
                __nv_bfloat162 pA = __float22bfloat162_rn(
                    make_float2(ev[ntA * 2] * inv, ev[ntA * 2 + 1] * inv));
                pa[kt][rr] = *(uint32_t*)&pA;
                if (ntB < 7) {
                    __nv_bfloat162 pB = __float22bfloat162_rn(
                        make_float2(ev[ntB * 2] * inv, ev[ntB * 2 + 1] * inv));
                    pa[kt][2 + rr] = *(uint32_t*)&pB;
                } else {
                    pa[kt][2 + rr] = 0u;
                }
            }
        }

        float o[4][4];
#pragma unroll
        for (int nd = 0; nd < 4; nd++)
#pragma unroll
            for (int c = 0; c < 4; c++) o[nd][c] = 0.0f;
#pragma unroll
        for (int kt = 0; kt < 4; kt++)
#pragma unroll
            for (int nd = 0; nd < 4; nd++) mma16816(o[nd], pa[kt], vb[kt][nd]);

#pragma unroll
        for (int rr = 0; rr < 2; rr++) {
            int q = mt * 16 + g + rr * 8;
            if (q < NTOK) {
#pragma unroll
                for (int nd = 0; nd < 4; nd++) {
                    __nv_bfloat162 p2 = __float22bfloat162_rn(
                        make_float2(o[nd][rr * 2], o[nd][rr * 2 + 1]));
                    *(uint32_t*)(g_ao + base + (size_t)q * Cc + hc + nd * 8 + tg * 2) =
                        *(uint32_t*)&p2;
                }
            }
        }
    }
}

// ---------------- launch ----------------
extern "C" void kernel_launch(void* const* d_in, const int* in_sizes, int n_in,
                              void* d_out, int out_size) {
    const float* x   = (const float*)d_in[0];
    const float* v   = (const float*)d_in[1];
    const float* n1g = (const float*)d_in[2];
    const float* n1b = (const float*)d_in[3];
    const float* nvg = (const float*)d_in[4];
    const float* nvb = (const float*)d_in[5];
    const float* qw  = (const float*)d_in[6];
    const float* qb  = (const float*)d_in[7];
    const float* kvw = (const float*)d_in[8];
    const float* kvb = (const float*)d_in[9];
    const float* rpb = (const float*)d_in[10];
    const float* pw  = (const float*)d_in[11];
    const float* pb  = (const float*)d_in[12];
    const float* n2g = (const float*)d_in[13];
    const float* n2b = (const float*)d_in[14];
    const float* f1w = (const float*)d_in[15];
    const float* f1b = (const float*)d_in[16];
    const float* f2w = (const float*)d_in[17];
    const float* f2b = (const float*)d_in[18];
    float* out = (float*)d_out;

    constexpr int GX = T / (128 * MIT);          // 392
    constexpr int ML1_SMEM = 80 * 1024;
    constexpr int ML2_SMEM = 96 * 1024;
    constexpr int FC2_SMEM = 192 * 1024;
    cudaFuncSetAttribute(gemm_ml<1, 4>, cudaFuncAttributeMaxDynamicSharedMemorySize, ML1_SMEM);
    cudaFuncSetAttribute(gemm_ml<1, 2>, cudaFuncAttributeMaxDynamicSharedMemorySize, ML1_SMEM);
    cudaFuncSetAttribute(gemm_ml<2, 3>, cudaFuncAttributeMaxDynamicSharedMemorySize, ML2_SMEM);
    cudaFuncSetAttribute(gemm_fc2, cudaFuncAttributeMaxDynamicSharedMemorySize, FC2_SMEM);

    cvt_all<<<(Cc * MLPH + 255) / 256, 256>>>(qw, kvw, pw, f1w, f2w);
    ln1_kernel<<<T / 8, 256>>>(x, v, n1g, n1b, nvg, nvb);
    gemm_ml<1, 4><<<dim3(GX, 6), 256, ML1_SMEM>>>(qb, kvb);          // q + kv merged
    attn_kernel<<<NWIN, 128>>>(rpb);
    gemm_ml<1, 2><<<dim3(GX, 2), 256, ML1_SMEM>>>(pb, nullptr);      // proj -> po (bf16)
    ln2_kernel<<<T / 8, 256>>>(x, n2g, n2b);                         // LN(x + po)
    gemm_ml<2, 3><<<dim3(GX, 4), 256, ML2_SMEM>>>(f1b, nullptr);     // fc1 + gelu
    gemm_fc2<<<GX, 256, FC2_SMEM>>>(f2b, x, out);                    // fc2 + x + po
}

// round 16
// speedup vs baseline: 1.1635x; 1.0424x over previous
#include <cuda_runtime.h>
#include <cuda_bf16.h>
#include <cstdint>

// ---------------- problem constants ----------------
constexpr int Bsz   = 16;
constexpr int Hdim  = 112;
constexpr int Wdim  = 112;
constexpr int Cc    = 128;
constexpr int HEADS = 4;
constexpr int HD    = 32;
constexpr int WS    = 7;
constexpr int L     = Hdim * Wdim;        // 12544
constexpr int T     = Bsz * L;            // 200704
constexpr int NTOK  = WS * WS;            // 49
constexpr int WPB   = (Hdim / WS) * (Wdim / WS);  // 256
constexpr int NWIN  = Bsz * WPB;          // 4096
constexpr int MLPH  = 512;
constexpr int MIT   = 4;
constexpr float SCALE = 0.17677669529663687f;
constexpr float EPS   = 1e-5f;

// ---------------- device scratch ----------------
__device__ __align__(16) __nv_bfloat16 g_xn[T * Cc];
__device__ __align__(16) __nv_bfloat16 g_vn[T * Cc];
__device__ __align__(16) __nv_bfloat16 g_q [T * Cc];
__device__ __align__(16) __nv_bfloat16 g_k [T * Cc];
__device__ __align__(16) __nv_bfloat16 g_v [T * Cc];
__device__ __align__(16) __nv_bfloat16 g_ao[T * Cc];
__device__ __align__(16) __nv_bfloat16 g_po[T * Cc];
__device__ __align__(16) __nv_bfloat16 g_xon[T * Cc];
__device__ __align__(16) __nv_bfloat16 g_h1[(size_t)T * MLPH];
__device__ __align__(16) __nv_bfloat16 g_qw [Cc * Cc];
__device__ __align__(16) __nv_bfloat16 g_kvw[2 * Cc * Cc];
__device__ __align__(16) __nv_bfloat16 g_pw [Cc * Cc];
__device__ __align__(16) __nv_bfloat16 g_f1w[MLPH * Cc];
__device__ __align__(16) __nv_bfloat16 g_f2w[Cc * MLPH];

// ---------------- helpers ----------------
__device__ __forceinline__ uint32_t s2u(const void* p) {
    return (uint32_t)__cvta_generic_to_shared(p);
}
__device__ __forceinline__ void ldsm4(uint32_t& r0, uint32_t& r1, uint32_t& r2,
                                      uint32_t& r3, uint32_t addr) {
    asm volatile("ldmatrix.sync.aligned.m8n8.x4.shared.b16 {%0,%1,%2,%3},[%4];"
                 : "=r"(r0), "=r"(r1), "=r"(r2), "=r"(r3) : "r"(addr));
}
__device__ __forceinline__ void cpasync16(uint32_t dst, const void* src) {
    asm volatile("cp.async.cg.shared.global [%0], [%1], 16;" :: "r"(dst), "l"(src));
}
__device__ __forceinline__ void cpcommit() { asm volatile("cp.async.commit_group;"); }
__device__ __forceinline__ void cpwait0()  { asm volatile("cp.async.wait_group 0;"); }

__device__ __forceinline__ void mma16816(float* c, const uint32_t* a, const uint32_t* b) {
    asm volatile(
        "mma.sync.aligned.m16n8k16.row.col.f32.bf16.bf16.f32 "
        "{%0,%1,%2,%3},{%4,%5,%6,%7},{%8,%9},{%0,%1,%2,%3};"
        : "+f"(c[0]), "+f"(c[1]), "+f"(c[2]), "+f"(c[3])
        : "r"(a[0]), "r"(a[1]), "r"(a[2]), "r"(a[3]), "r"(b[0]), "r"(b[1]));
}
__device__ __forceinline__ uint32_t swoff(int row, int c) {
    return ((uint32_t)row << 8) + (uint32_t)((c ^ (row & 7)) << 4);
}

// ---------------- weight conversion ----------------
__global__ void cvt_all(const float* __restrict__ qw, const float* __restrict__ kvw,
                        const float* __restrict__ pw, const float* __restrict__ f1w,
                        const float* __restrict__ f2w) {
    int i = blockIdx.x * blockDim.x + threadIdx.x;
    if (i < Cc * Cc)     g_qw[i]  = __float2bfloat16(qw[i]);
    if (i < 2 * Cc * Cc) g_kvw[i] = __float2bfloat16(kvw[i]);
    if (i < Cc * Cc)     g_pw[i]  = __float2bfloat16(pw[i]);
    if (i < MLPH * Cc)   g_f1w[i] = __float2bfloat16(f1w[i]);
    if (i < Cc * MLPH)   g_f2w[i] = __float2bfloat16(f2w[i]);
}

// ---------------- LayerNorm ----------------
__device__ __forceinline__ void ln_finish(const float4& xv, float s, float q,
                                          const float4& g, const float4& b,
                                          __nv_bfloat16* dst, size_t off) {
    float mu = s * (1.0f / Cc);
    float var = q * (1.0f / Cc) - mu * mu;
    float r = rsqrtf(var + EPS);
    __nv_bfloat162 p0 = {__float2bfloat16((xv.x - mu) * r * g.x + b.x),
                         __float2bfloat16((xv.y - mu) * r * g.y + b.y)};
    __nv_bfloat162 p1 = {__float2bfloat16((xv.z - mu) * r * g.z + b.z),
                         __float2bfloat16((xv.w - mu) * r * g.w + b.w)};
    uint2 out;
    out.x = *(uint32_t*)&p0;
    out.y = *(uint32_t*)&p1;
    *(uint2*)(dst + off) = out;
}

__global__ void __launch_bounds__(256) ln1_kernel(
    const float* __restrict__ x, const float* __restrict__ v,
    const float* __restrict__ g1, const float* __restrict__ b1,
    const float* __restrict__ gv, const float* __restrict__ bv) {
    int warp = threadIdx.x >> 5, lane = threadIdx.x & 31;
    int t = blockIdx.x * 8 + warp;
    int b = t / L, l = t - b * L;
    int row = l / Wdim, col = l - row * Wdim;
    int wy = row / WS, iy = row - wy * WS;
    int wx = col / WS, ix = col - wx * WS;
    int wt = ((b * WPB) + wy * 16 + wx) * NTOK + iy * WS + ix;

    float4 xv = ((const float4*)(x + (size_t)t * Cc))[lane];
    float4 vv = ((const float4*)(v + (size_t)t * Cc))[lane];
    float4 gx = ((const float4*)g1)[lane];
    float4 bx = ((const float4*)b1)[lane];
    float4 gvv = ((const float4*)gv)[lane];
    float4 bvv = ((const float4*)bv)[lane];

    float sx = xv.x + xv.y + xv.z + xv.w;
    float qx = xv.x * xv.x + xv.y * xv.y + xv.z * xv.z + xv.w * xv.w;
    float sv = vv.x + vv.y + vv.z + vv.w;
    float qv = vv.x * vv.x + vv.y * vv.y + vv.z * vv.z + vv.w * vv.w;
#pragma unroll
    for (int o = 16; o; o >>= 1) {
        sx += __shfl_xor_sync(0xffffffffu, sx, o);
        qx += __shfl_xor_sync(0xffffffffu, qx, o);
        sv += __shfl_xor_sync(0xffffffffu, sv, o);
        qv += __shfl_xor_sync(0xffffffffu, qv, o);
    }
    size_t off = (size_t)wt * Cc + lane * 4;
    ln_finish(xv, sx, qx, gx, bx, g_xn, off);
    ln_finish(vv, sv, qv, gvv, bvv, g_vn, off);
}

__global__ void __launch_bounds__(256) ln2_kernel(
    const float* __restrict__ x,
    const float* __restrict__ g2, const float* __restrict__ b2) {
    int warp = threadIdx.x >> 5, lane = threadIdx.x & 31;
    int t = blockIdx.x * 8 + warp;

    float4 a = ((const float4*)(x + (size_t)t * Cc))[lane];
    uint2 pr = *(const uint2*)(g_po + (size_t)t * Cc + lane * 4);
    __nv_bfloat162 p0 = *(__nv_bfloat162*)&pr.x;
    __nv_bfloat162 p1 = *(__nv_bfloat162*)&pr.y;
    a.x += __bfloat162float(p0.x);
    a.y += __bfloat162float(p0.y);
    a.z += __bfloat162float(p1.x);
    a.w += __bfloat162float(p1.y);
    float4 g = ((const float4*)g2)[lane];
    float4 b = ((const float4*)b2)[lane];

    float s = a.x + a.y + a.z + a.w;
    float q = a.x * a.x + a.y * a.y + a.z * a.z + a.w * a.w;
#pragma unroll
    for (int o = 16; o; o >>= 1) {
        s += __shfl_xor_sync(0xffffffffu, s, o);
        q += __shfl_xor_sync(0xffffffffu, q, o);
    }
    ln_finish(a, s, q, g, b, g_xon, (size_t)t * Cc + lane * 4);
}

// ---------------- M-looped GEMM ----------------
// EPI: 2=PROJ(->po bf16, scatter)  3=FC1(gelu)  4=QKV merged (y<2: q, else kv)
template <int NTILES, int EPI>
__global__ void __launch_bounds__(256, 2) gemm_ml(const float* __restrict__ bias,
                                                  const float* __restrict__ bias2) {
    extern __shared__ __nv_bfloat16 sm[];
    const uint32_t sA_u[2] = {s2u(sm), s2u(sm) + 32768};
    const uint32_t sB_u = s2u(sm) + 65536;

    const bool isq = (EPI == 4) && (blockIdx.y < 2);
    const __nv_bfloat16* A =
        (EPI == 2) ? g_ao : (EPI == 3) ? g_xon : (isq ? g_xn : g_vn);
    const __nv_bfloat16* W =
        (EPI == 2) ? g_pw : (EPI == 3) ? g_f1w : (isq ? g_qw : g_kvw);
    const float* bptr = (EPI == 4) ? (isq ? bias : bias2) : bias;

    const int tid = threadIdx.x, warp = tid >> 5, lane = tid & 31;
    const int mbase = blockIdx.x * (128 * MIT);
    const int yb = (EPI == 4) ? (isq ? blockIdx.y : blockIdx.y - 2) : blockIdx.y;
    const int n0 = yb * (64 * NTILES);
    const int wm = (warp & 3) * 32, wn = (warp >> 2) * 32;
    const int g = lane >> 2, tg = lane & 3;
    const int a_row = wm + (lane & 15), a_ch = lane >> 4;
    const int b_row = wn + ((lane >> 4) << 3) + (lane & 7), b_ch = (lane >> 3) & 1;

    float breg[NTILES][8];
#pragma unroll
    for (int nt = 0; nt < NTILES; nt++)
#pragma unroll
        for (int ni = 0; ni < 4; ni++)
#pragma unroll
            for (int cc = 0; cc < 2; cc++)
                breg[nt][ni * 2 + cc] =
                    __ldg(bptr + n0 + nt * 64 + wn + ni * 8 + tg * 2 + cc);

#pragma unroll
    for (int i = 0; i < 4 * NTILES; i++) {
        int idx = tid + i * 256;
        int bt = idx >> 10, rem = idx & 1023;
        int row = rem >> 4, c = rem & 15;
        cpasync16(sB_u + bt * 16384 + swoff(row, c),
                  W + (size_t)(n0 + bt * 64 + row) * Cc + c * 8);
    }
#pragma unroll
    for (int i = 0; i < 8; i++) {
        int idx = tid + i * 256;
        int row = idx >> 4, c = idx & 15;
        cpasync16(sA_u[0] + swoff(row, c), A + (size_t)(mbase + row) * Cc + c * 8);
    }
    cpcommit();

    for (int mt = 0; mt < MIT; mt++) {
        cpwait0();
        __syncthreads();
        if (mt + 1 < MIT) {
            const int mn = mbase + (mt + 1) * 128;
#pragma unroll
            for (int i = 0; i < 8; i++) {
                int idx = tid + i * 256;
                int row = idx >> 4, c = idx & 15;
                cpasync16(sA_u[(mt + 1) & 1] + swoff(row, c),
                          A + (size_t)(mn + row) * Cc + c * 8);
            }
            cpcommit();
        }
        const uint32_t sAc = sA_u[mt & 1];
        const int m0 = mbase + mt * 128;

#pragma unroll
        for (int nt = 0; nt < NTILES; nt++) {
            const uint32_t sBc = sB_u + nt * 16384;
            const int nc0 = n0 + nt * 64;

            float acc[2][4][4];
#pragma unroll
            for (int a = 0; a < 2; a++)
#pragma unroll
                for (int b = 0; b < 4; b++)
#pragma unroll
                    for (int c = 0; c < 4; c++) acc[a][b][c] = 0.0f;

#pragma unroll
            for (int kh = 0; kh < 8; kh++) {
                uint32_t a[2][4];
#pragma unroll
                for (int mi = 0; mi < 2; mi++) {
                    int row = a_row + mi * 16;
                    int ch = (2 * kh + a_ch) ^ (row & 7);
                    ldsm4(a[mi][0], a[mi][1], a[mi][2], a[mi][3],
                          sAc + ((uint32_t)row << 8) + (uint32_t)(ch << 4));
                }
                uint32_t b[2][4];
#pragma unroll
                for (int nj = 0; nj < 2; nj++) {
                    int row = b_row + nj * 16;
                    int ch = (2 * kh + b_ch) ^ (row & 7);
                    ldsm4(b[nj][0], b[nj][1], b[nj][2], b[nj][3],
                          sBc + ((uint32_t)row << 8) + (uint32_t)(ch << 4));
                }
#pragma unroll
                for (int mi = 0; mi < 2; mi++)
#pragma unroll
                    for (int ni = 0; ni < 4; ni++) {
                        uint32_t bb[2] = {b[ni >> 1][(ni & 1) * 2],
                                          b[ni >> 1][(ni & 1) * 2 + 1]};
                        mma16816(acc[mi][ni], a[mi], bb);
                    }
            }

#pragma unroll
            for (int mi = 0; mi < 2; mi++)
#pragma unroll
                for (int rr = 0; rr < 2; rr++) {
                    int row = m0 + wm + mi * 16 + g + rr * 8;
                    if (EPI == 4 && isq) {
#pragma unroll
                        for (int ni = 0; ni < 4; ni++) {
                            float v0 = (acc[mi][ni][rr * 2] + breg[nt][ni * 2]) * SCALE;
                            float v1 = (acc[mi][ni][rr * 2 + 1] + breg[nt][ni * 2 + 1]) * SCALE;
                            __nv_bfloat162 p = __float22bfloat162_rn(make_float2(v0, v1));
                            *(uint32_t*)(g_q + (size_t)row * Cc + nc0 + wn + ni * 8 + tg * 2) =
                                *(uint32_t*)&p;
                        }
                    } else if (EPI == 4) {
                        __nv_bfloat16* dst = (nc0 < Cc) ? g_k : g_v;
                        const int nb = (nc0 < Cc) ? nc0 : nc0 - Cc;
#pragma unroll
                        for (int ni = 0; ni < 4; ni++) {
                            float v0 = acc[mi][ni][rr * 2] + breg[nt][ni * 2];
                            float v1 = acc[mi][ni][rr * 2 + 1] + breg[nt][ni * 2 + 1];
                            __nv_bfloat162 p = __float22bfloat162_rn(make_float2(v0, v1));
                            *(uint32_t*)(dst + (size_t)row * Cc + nb + wn + ni * 8 + tg * 2) =
                                *(uint32_t*)&p;
                        }
                    } else if (EPI == 2) {
                        int win = row / NTOK, n = row - win * NTOK;
                        int b = win >> 8, wr = win & 255;
                        int wy = wr >> 4, wx = wr & 15;
                        int iy = n / WS, ix = n - iy * WS;
                        int trow = b * L + (wy * WS + iy) * Wdim + wx * WS + ix;
#pragma unroll
                        for (int ni = 0; ni < 4; ni++) {
                            float v0 = acc[mi][ni][rr * 2] + breg[nt][ni * 2];
                            float v1 = acc[mi][ni][rr * 2 + 1] + breg[nt][ni * 2 + 1];
                            __nv_bfloat162 p = __float22bfloat162_rn(make_float2(v0, v1));
                            *(uint32_t*)(g_po + (size_t)trow * Cc + nc0 + wn + ni * 8 + tg * 2) =
                                *(uint32_t*)&p;
                        }
                    } else {
#pragma unroll
                        for (int ni = 0; ni < 4; ni++) {
                            float v0 = acc[mi][ni][rr * 2] + breg[nt][ni * 2];
                            float v1 = acc[mi][ni][rr * 2 + 1] + breg[nt][ni * 2 + 1];
                            v0 = 0.5f * v0 * (1.0f + erff(v0 * 0.70710678118654752f));
                            v1 = 0.5f * v1 * (1.0f + erff(v1 * 0.70710678118654752f));
                            __nv_bfloat162 p = __float22bfloat162_rn(make_float2(v0, v1));
                            *(uint32_t*)(g_h1 + (size_t)row * MLPH + nc0 + wn + ni * 8 + tg * 2) =
                                *(uint32_t*)&p;
                        }
                    }
                }
        }
    }
}

// ---------------- fc2: full weight resident, out = acc + b2 + x + po ----------------
__global__ void __launch_bounds__(256) gemm_fc2(const float* __restrict__ bias,
                                                const float* __restrict__ xres,
                                                float* __restrict__ outf) {
    extern __shared__ __nv_bfloat16 sm[];
    const uint32_t sA_u[2] = {s2u(sm), s2u(sm) + 32768};
    const uint32_t sB_u = s2u(sm) + 65536;

    const int tid = threadIdx.x, warp = tid >> 5, lane = tid & 31;
    const int mbase = blockIdx.x * (128 * MIT);
    const int wm = (warp & 3) * 32, wn = (warp >> 2) * 32;
    const int g = lane >> 2, tg = lane & 3;
    const int a_row = wm + (lane & 15), a_ch = lane >> 4;
    const int b_row = wn + ((lane >> 4) << 3) + (lane & 7), b_ch = (lane >> 3) & 1;

    float breg[2][8];
#pragma unroll
    for (int nt = 0; nt < 2; nt++)
#pragma unroll
        for (int ni = 0; ni < 4; ni++)
#pragma unroll
            for (int cc = 0; cc < 2; cc++)
                breg[nt][ni * 2 + cc] = __ldg(bias + nt * 64 + wn + ni * 8 + tg * 2 + cc);

#pragma unroll
    for (int i = 0; i < 32; i++) {
        int idx = tid + i * 256;
        int bt = idx >> 10, rem = idx & 1023;
        int kc = bt >> 1, nt = bt & 1;
        int row = rem >> 4, c = rem & 15;
        cpasync16(sB_u + bt * 16384 + swoff(row, c),
                  g_f2w + (size_t)(nt * 64 + row) * MLPH + kc * 128 + c * 8);
    }
#pragma unroll
    for (int i = 0; i < 8; i++) {
        int idx = tid + i * 256;
        int row = idx >> 4, c = idx & 15;
        cpasync16(sA_u[0] + swoff(row, c), g_h1 + (size_t)(mbase + row) * MLPH + c * 8);
    }
    cpcommit();

    float acc[2][2][4][4];
    constexpr int NSTEP = MIT * 4;
    for (int step = 0; step < NSTEP; step++) {
        const int mt = step >> 2, kc = step & 3;
        cpwait0();
        __syncthreads();
        if (step + 1 < NSTEP) {
            const int nmt = (step + 1) >> 2, nkc = (step + 1) & 3;
            const int mrow = mbase + nmt * 128;
#pragma unroll
            for (int i = 0; i < 8; i++) {
                int idx = tid + i * 256;
                int row = idx >> 4, c = idx & 15;
                cpasync16(sA_u[(step + 1) & 1] + swoff(row, c),
                          g_h1 + (size_t)(mrow + row) * MLPH + nkc * 128 + c * 8);
            }
            cpcommit();
        }
        if (kc == 0) {
#pragma unroll
            for (int t = 0; t < 2; t++)
#pragma unroll
                for (int a = 0; a < 2; a++)
#pragma unroll
                    for (int b = 0; b < 4; b++)
#pragma unroll
                        for (int c = 0; c < 4; c++) acc[t][a][b][c] = 0.0f;
        }
        const uint32_t sAc = sA_u[step & 1];

#pragma unroll
        for (int kh = 0; kh < 8; kh++) {
            uint32_t a[2][4];
#pragma unroll
            for (int mi = 0; mi < 2; mi++) {
                int row = a_row + mi * 16;
                int ch = (2 * kh + a_ch) ^ (row & 7);
                ldsm4(a[mi][0], a[mi][1], a[mi][2], a[mi][3],
                      sAc + ((uint32_t)row << 8) + (uint32_t)(ch << 4));
            }
#pragma unroll
            for (int nt = 0; nt < 2; nt++) {
                const uint32_t sBc = sB_u + (kc * 2 + nt) * 16384;
                uint32_t b[2][4];
#pragma unroll
                for (int nj = 0; nj < 2; nj++) {
                    int row = b_row + nj * 16;
                    int ch = (2 * kh + b_ch) ^ (row & 7);
                    ldsm4(b[nj][0], b[nj][1], b[nj][2], b[nj][3],
                          sBc + ((uint32_t)row << 8) + (uint32_t)(ch << 4));
                }
#pragma unroll
                for (int mi = 0; mi < 2; mi++)
#pragma unroll
                    for (int ni = 0; ni < 4; ni++) {
                        uint32_t bb[2] = {b[ni >> 1][(ni & 1) * 2],
                                          b[ni >> 1][(ni & 1) * 2 + 1]};
                        mma16816(acc[nt][mi][ni], a[mi], bb);
                    }
            }
        }

        if (kc == 3) {
            const int m0 = mbase + mt * 128;
#pragma unroll
            for (int nt = 0; nt < 2; nt++)
#pragma unroll
                for (int mi = 0; mi < 2; mi++)
#pragma unroll
                    for (int rr = 0; rr < 2; rr++) {
                        int row = m0 + wm + mi * 16 + g + rr * 8;
#pragma unroll
                        for (int ni = 0; ni < 4; ni++) {
                            size_t oi = (size_t)row * Cc + nt * 64 + wn + ni * 8 + tg * 2;
                            float2 xv = *(const float2*)(xres + oi);
                            __nv_bfloat162 pv = *(const __nv_bfloat162*)(g_po + oi);
                            float2 ov;
                            ov.x = acc[nt][mi][ni][rr * 2] + breg[nt][ni * 2] + xv.x +
                                   __bfloat162float(pv.x);
                            ov.y = acc[nt][mi][ni][rr * 2 + 1] + breg[nt][ni * 2 + 1] + xv.y +
                                   __bfloat162float(pv.y);
                            *(float2*)(outf + oi) = ov;
                        }
                    }
        }
    }
}

// ---------------- tensor-core windowed attention (phased registers) ----------------
__global__ void __launch_bounds__(128) attn_kernel(const float* __restrict__ rpb) {
    constexpr int SST = 136;
    __shared__ __nv_bfloat16 sK[64 * SST];
    __shared__ __nv_bfloat16 sV[64 * SST];
    __shared__ float sb[HEADS * 169];

    const int win = blockIdx.x;
    const int tid = threadIdx.x, warp = tid >> 5, lane = tid & 31;
    const int g = lane >> 2, tg = lane & 3;
    const size_t base = (size_t)win * NTOK * Cc;

    // K/V staging via cp.async (no LDG->reg->STS round trip)
    for (int i = tid; i < 49 * 16; i += 128) {
        int r = i >> 4, cb = (i & 15) * 8;
        cpasync16(s2u(&sK[r * SST + cb]), g_k + base + (size_t)r * Cc + cb);
        cpasync16(s2u(&sV[r * SST + cb]), g_v + base + (size_t)r * Cc + cb);
    }
    for (int i = tid; i < 15 * 16; i += 128) {  // zero V pad rows
        int r = 49 + (i >> 4), cb = (i & 15) * 8;
        *(uint4*)&sV[r * SST + cb] = make_uint4(0, 0, 0, 0);
    }
    for (int i = lane; i < 169; i += 32) sb[warp * 169 + i] = rpb[i * HEADS + warp];
    cpcommit();
    cpwait0();
    __syncthreads();

    const int hc = warp * HD;
    const float* sbh = &sb[warp * 169];

#pragma unroll
    for (int mt = 0; mt < 4; mt++) {
        uint32_t qa[2][4];
        int q0 = win * NTOK + mt * 16 + g;
        int q1 = q0 + 8;
        int q0c = q0 < T ? q0 : T - 1;
        int q1c = q1 < T ? q1 : T - 1;
#pragma unroll
        for (int kh = 0; kh < 2; kh++) {
            const __nv_bfloat16* p0 = g_q + (size_t)q0c * Cc + hc + kh * 16 + tg * 2;
            const __nv_bfloat16* p1 = g_q + (size_t)q1c * Cc + hc + kh * 16 + tg * 2;
            qa[kh][0] = *(const uint32_t*)p0;
            qa[kh][1] = *(const uint32_t*)p1;
            qa[kh][2] = *(const uint32_t*)(p0 + 8);
            qa[kh][3] = *(const uint32_t*)(p1 + 8);
        }

        // phase 1: QK^T — K frags loaded here, die after this block
        float s[7][4];
#pragma unroll
        for (int nt = 0; nt < 7; nt++)
#pragma unroll
            for (int c = 0; c < 4; c++) s[nt][c] = 0.0f;
#pragma unroll
        for (int kh = 0; kh < 2; kh++)
#pragma unroll
            for (int nt = 0; nt < 7; nt++) {
                const __nv_bfloat16* p = &sK[(nt * 8 + g) * SST + hc + kh * 16 + tg * 2];
                uint32_t kb[2];
                kb[0] = *(const uint32_t*)p;
                kb[1] = *(const uint32_t*)(p + 8);
                mma16816(s[nt], qa[kh], kb);
            }

        uint32_t pa[4][4];
#pragma unroll
        for (int rr = 0; rr < 2; rr++) {
            int q = mt * 16 + g + rr * 8;
            int qq = q < NTOK ? q : NTOK - 1;
            int qy = qq / WS, qx = qq - qy * WS;
            float ev[14];
            float mx = -1e30f;
#pragma unroll
            for (int nt = 0; nt < 7; nt++)
#pragma unroll
                for (int cc = 0; cc < 2; cc++) {
                    int key = nt * 8 + tg * 2 + cc;
                    float v = s[nt][rr * 2 + cc];
                    if (key < NTOK) {
                        int ky = key / WS, kx = key - ky * WS;
                        v += sbh[(qy - ky + 6) * 13 + (qx - kx + 6)];
                        mx = fmaxf(mx, v);
                    }
                    ev[nt * 2 + cc] = v;
                }
            mx = fmaxf(mx, __shfl_xor_sync(0xffffffffu, mx, 1));
            mx = fmaxf(mx, __shfl_xor_sync(0xffffffffu, mx, 2));
            float sum = 0.0f;
#pragma unroll
            for (int j = 0; j < 14; j++) {
                int key = (j >> 1) * 8 + tg * 2 + (j & 1);
                float e = (key < NTOK) ? __expf(ev[j] - mx) : 0.0f;
                ev[j] = e;
                sum += e;
            }
            sum += __shfl_xor_sync(0xffffffffu, sum, 1);
            sum += __shfl_xor_sync(0xffffffffu, sum, 2);
            float inv = 1.0f / sum;
#pragma unroll
            for (int kt = 0; kt < 4; kt++) {
                int ntA = 2 * kt, ntB = 2 * kt + 1;
                __nv_bfloat162 pA = __float22bfloat162_rn(
                    make_float2(ev[ntA * 2] * inv, ev[ntA * 2 + 1] * inv));
                pa[kt][rr] = *(uint32_t*)&pA;
                if (ntB < 7) {
                    __nv_bfloat162 pB = __float22bfloat162_rn(
                        make_float2(ev[ntB * 2] * inv, ev[ntB * 2 + 1] * inv));
                    pa[kt][2 + rr] = *(uint32_t*)&pB;
                } else {
                    pa[kt][2 + rr] = 0u;
                }
            }
        }

        // phase 2: P@V — V frags loaded here, die after this block
        float o[4][4];
#pragma unroll
        for (int nd = 0; nd < 4; nd++)
#pragma unroll
            for (int c = 0; c < 4; c++) o[nd][c] = 0.0f;
#pragma unroll
        for (int kt = 0; kt < 4; kt++)
#pragma unroll
            for (int nd = 0; nd < 4; nd++) {
                int k0 = kt * 16 + tg * 2;
                int c = hc + nd * 8 + g;
                __nv_bfloat162 b0 = {sV[k0 * SST + c], sV[(k0 + 1) * SST + c]};
                __nv_bfloat162 b1 = {sV[(k0 + 8) * SST + c], sV[(k0 + 9) * SST + c]};
                uint32_t vb[2];
                vb[0] = *(uint32_t*)&b0;
                vb[1] = *(uint32_t*)&b1;
                mma16816(o[nd], pa[kt], vb);
            }

#pragma unroll
        for (int rr = 0; rr < 2; rr++) {
            int q = mt * 16 + g + rr * 8;
            if (q < NTOK) {
#pragma unroll
                for (int nd = 0; nd < 4; nd++) {
                    __nv_bfloat162 p2 = __float22bfloat162_rn(
                        make_float2(o[nd][rr * 2], o[nd][rr * 2 + 1]));
                    *(uint32_t*)(g_ao + base + (size_t)q * Cc + hc + nd * 8 + tg * 2) =
                        *(uint32_t*)&p2;
                }
            }
        }
    }
}

// ---------------- launch ----------------
extern "C" void kernel_launch(void* const* d_in, const int* in_sizes, int n_in,
                              void* d_out, int out_size) {
    const float* x   = (const float*)d_in[0];
    const float* v   = (const float*)d_in[1];
    const float* n1g = (const float*)d_in[2];
    const float* n1b = (const float*)d_in[3];
    const float* nvg = (const float*)d_in[4];
    const float* nvb = (const float*)d_in[5];
    const float* qw  = (const float*)d_in[6];
    const float* qb  = (const float*)d_in[7];
    const float* kvw = (const float*)d_in[8];
    const float* kvb = (const float*)d_in[9];
    const float* rpb = (const float*)d_in[10];
    const float* pw  = (const float*)d_in[11];
    const float* pb  = (const float*)d_in[12];
    const float* n2g = (const float*)d_in[13];
    const float* n2b = (const float*)d_in[14];
    const float* f1w = (const float*)d_in[15];
    const float* f1b = (const float*)d_in[16];
    const float* f2w = (const float*)d_in[17];
    const float* f2b = (const float*)d_in[18];
    float* out = (float*)d_out;

    constexpr int GX = T / (128 * MIT);          // 392
    constexpr int ML1_SMEM = 80 * 1024;
    constexpr int ML2_SMEM = 96 * 1024;
    constexpr int FC2_SMEM = 192 * 1024;
    cudaFuncSetAttribute(gemm_ml<1, 4>, cudaFuncAttributeMaxDynamicSharedMemorySize, ML1_SMEM);
    cudaFuncSetAttribute(gemm_ml<1, 2>, cudaFuncAttributeMaxDynamicSharedMemorySize, ML1_SMEM);
    cudaFuncSetAttribute(gemm_ml<2, 3>, cudaFuncAttributeMaxDynamicSharedMemorySize, ML2_SMEM);
    cudaFuncSetAttribute(gemm_fc2, cudaFuncAttributeMaxDynamicSharedMemorySize, FC2_SMEM);

    cvt_all<<<(Cc * MLPH + 255) / 256, 256>>>(qw, kvw, pw, f1w, f2w);
    ln1_kernel<<<T / 8, 256>>>(x, v, n1g, n1b, nvg, nvb);
    gemm_ml<1, 4><<<dim3(GX, 6), 256, ML1_SMEM>>>(qb, kvb);          // q + kv merged
    attn_kernel<<<NWIN, 128>>>(rpb);
    gemm_ml<1, 2><<<dim3(GX, 2), 256, ML1_SMEM>>>(pb, nullptr);      // proj -> po
    ln2_kernel<<<T / 8, 256>>>(x, n2g, n2b);                         // LN(x + po)
    gemm_ml<2, 3><<<dim3(GX, 4), 256, ML2_SMEM>>>(f1b, nullptr);     // fc1 + gelu
    gemm_fc2<<<GX, 256, FC2_SMEM>>>(f2b, x, out);                    // fc2 + x + po
}

// round 17
// speedup vs baseline: 1.1824x; 1.0162x over previous
#include <cuda_runtime.h>
#include <cuda_bf16.h>
#include <cstdint>

// ---------------- problem constants ----------------
constexpr int Bsz   = 16;
constexpr int Hdim  = 112;
constexpr int Wdim  = 112;
constexpr int Cc    = 128;
constexpr int HEADS = 4;
constexpr int HD    = 32;
constexpr int WS    = 7;
constexpr int L     = Hdim * Wdim;        // 12544
constexpr int T     = Bsz * L;            // 200704
constexpr int NTOK  = WS * WS;            // 49
constexpr int WPB   = (Hdim / WS) * (Wdim / WS);  // 256
constexpr int NWIN  = Bsz * WPB;          // 4096
constexpr int MLPH  = 512;
constexpr int MIT   = 4;
constexpr float SCALE = 0.17677669529663687f;
constexpr float EPS   = 1e-5f;

// ---------------- device scratch ----------------
__device__ __align__(16) __nv_bfloat16 g_xn[T * Cc];
__device__ __align__(16) __nv_bfloat16 g_vn[T * Cc];
__device__ __align__(16) __nv_bfloat16 g_q [T * Cc];
__device__ __align__(16) __nv_bfloat16 g_k [T * Cc];
__device__ __align__(16) __nv_bfloat16 g_v [T * Cc];
__device__ __align__(16) __nv_bfloat16 g_ao[T * Cc];
__device__ __align__(16) __nv_bfloat16 g_po[T * Cc];
__device__ __align__(16) __nv_bfloat16 g_xon[T * Cc];
__device__ __align__(16) __nv_bfloat16 g_h1[(size_t)T * MLPH];
__device__ __align__(16) __nv_bfloat16 g_qw [Cc * Cc];
__device__ __align__(16) __nv_bfloat16 g_kvw[2 * Cc * Cc];
__device__ __align__(16) __nv_bfloat16 g_pw [Cc * Cc];
__device__ __align__(16) __nv_bfloat16 g_f1w[MLPH * Cc];
__device__ __align__(16) __nv_bfloat16 g_f2w[Cc * MLPH];

// ---------------- helpers ----------------
__device__ __forceinline__ uint32_t s2u(const void* p) {
    return (uint32_t)__cvta_generic_to_shared(p);
}
__device__ __forceinline__ void ldsm4(uint32_t& r0, uint32_t& r1, uint32_t& r2,
                                      uint32_t& r3, uint32_t addr) {
    asm volatile("ldmatrix.sync.aligned.m8n8.x4.shared.b16 {%0,%1,%2,%3},[%4];"
                 : "=r"(r0), "=r"(r1), "=r"(r2), "=r"(r3) : "r"(addr));
}
__device__ __forceinline__ void cpasync16(uint32_t dst, const void* src) {
    asm volatile("cp.async.cg.shared.global [%0], [%1], 16;" :: "r"(dst), "l"(src));
}
__device__ __forceinline__ void cpcommit() { asm volatile("cp.async.commit_group;"); }
__device__ __forceinline__ void cpwait0()  { asm volatile("cp.async.wait_group 0;"); }

__device__ __forceinline__ void mma16816(float* c, const uint32_t* a, const uint32_t* b) {
    asm volatile(
        "mma.sync.aligned.m16n8k16.row.col.f32.bf16.bf16.f32 "
        "{%0,%1,%2,%3},{%4,%5,%6,%7},{%8,%9},{%0,%1,%2,%3};"
        : "+f"(c[0]), "+f"(c[1]), "+f"(c[2]), "+f"(c[3])
        : "r"(a[0]), "r"(a[1]), "r"(a[2]), "r"(a[3]), "r"(b[0]), "r"(b[1]));
}
__device__ __forceinline__ uint32_t swoff(int row, int c) {
    return ((uint32_t)row << 8) + (uint32_t)((c ^ (row & 7)) << 4);
}

// ---------------- weight conversion ----------------
__global__ void cvt_all(const float* __restrict__ qw, const float* __restrict__ kvw,
                        const float* __restrict__ pw, const float* __restrict__ f1w,
                        const float* __restrict__ f2w) {
    int i = blockIdx.x * blockDim.x + threadIdx.x;
    if (i < Cc * Cc)     g_qw[i]  = __float2bfloat16(qw[i]);
    if (i < 2 * Cc * Cc) g_kvw[i] = __float2bfloat16(kvw[i]);
    if (i < Cc * Cc)     g_pw[i]  = __float2bfloat16(pw[i]);
    if (i < MLPH * Cc)   g_f1w[i] = __float2bfloat16(f1w[i]);
    if (i < Cc * MLPH)   g_f2w[i] = __float2bfloat16(f2w[i]);
}

// ---------------- LayerNorm ----------------
__device__ __forceinline__ void ln_finish(const float4& xv, float s, float q,
                                          const float4& g, const float4& b,
                                          __nv_bfloat16* dst, size_t off) {
    float mu = s * (1.0f / Cc);
    float var = q * (1.0f / Cc) - mu * mu;
    float r = rsqrtf(var + EPS);
    __nv_bfloat162 p0 = {__float2bfloat16((xv.x - mu) * r * g.x + b.x),
                         __float2bfloat16((xv.y - mu) * r * g.y + b.y)};
    __nv_bfloat162 p1 = {__float2bfloat16((xv.z - mu) * r * g.z + b.z),
                         __float2bfloat16((xv.w - mu) * r * g.w + b.w)};
    uint2 out;
    out.x = *(uint32_t*)&p0;
    out.y = *(uint32_t*)&p1;
    *(uint2*)(dst + off) = out;
}

__global__ void __launch_bounds__(256) ln1_kernel(
    const float* __restrict__ x, const float* __restrict__ v,
    const float* __restrict__ g1, const float* __restrict__ b1,
    const float* __restrict__ gv, const float* __restrict__ bv) {
    int warp = threadIdx.x >> 5, lane = threadIdx.x & 31;
    int t = blockIdx.x * 8 + warp;
    int b = t / L, l = t - b * L;
    int row = l / Wdim, col = l - row * Wdim;
    int wy = row / WS, iy = row - wy * WS;
    int wx = col / WS, ix = col - wx * WS;
    int wt = ((b * WPB) + wy * 16 + wx) * NTOK + iy * WS + ix;

    float4 xv = ((const float4*)(x + (size_t)t * Cc))[lane];
    float4 vv = ((const float4*)(v + (size_t)t * Cc))[lane];
    float4 gx = ((const float4*)g1)[lane];
    float4 bx = ((const float4*)b1)[lane];
    float4 gvv = ((const float4*)gv)[lane];
    float4 bvv = ((const float4*)bv)[lane];

    float sx = xv.x + xv.y + xv.z + xv.w;
    float qx = xv.x * xv.x + xv.y * xv.y + xv.z * xv.z + xv.w * xv.w;
    float sv = vv.x + vv.y + vv.z + vv.w;
    float qv = vv.x * vv.x + vv.y * vv.y + vv.z * vv.z + vv.w * vv.w;
#pragma unroll
    for (int o = 16; o; o >>= 1) {
        sx += __shfl_xor_sync(0xffffffffu, sx, o);
        qx += __shfl_xor_sync(0xffffffffu, qx, o);
        sv += __shfl_xor_sync(0xffffffffu, sv, o);
        qv += __shfl_xor_sync(0xffffffffu, qv, o);
    }
    size_t off = (size_t)wt * Cc + lane * 4;
    ln_finish(xv, sx, qx, gx, bx, g_xn, off);
    ln_finish(vv, sv, qv, gvv, bvv, g_vn, off);
}

__global__ void __launch_bounds__(256) ln2_kernel(
    const float* __restrict__ x,
    const float* __restrict__ g2, const float* __restrict__ b2) {
    int warp = threadIdx.x >> 5, lane = threadIdx.x & 31;
    int t = blockIdx.x * 8 + warp;

    float4 a = ((const float4*)(x + (size_t)t * Cc))[lane];
    uint2 pr = *(const uint2*)(g_po + (size_t)t * Cc + lane * 4);
    __nv_bfloat162 p0 = *(__nv_bfloat162*)&pr.x;
    __nv_bfloat162 p1 = *(__nv_bfloat162*)&pr.y;
    a.x += __bfloat162float(p0.x);
    a.y += __bfloat162float(p0.y);
    a.z += __bfloat162float(p1.x);
    a.w += __bfloat162float(p1.y);
    float4 g = ((const float4*)g2)[lane];
    float4 b = ((const float4*)b2)[lane];

    float s = a.x + a.y + a.z + a.w;
    float q = a.x * a.x + a.y * a.y + a.z * a.z + a.w * a.w;
#pragma unroll
    for (int o = 16; o; o >>= 1) {
        s += __shfl_xor_sync(0xffffffffu, s, o);
        q += __shfl_xor_sync(0xffffffffu, q, o);
    }
    ln_finish(a, s, q, g, b, g_xon, (size_t)t * Cc + lane * 4);
}

// ---------------- M-looped GEMM ----------------
// EPI: 2=PROJ(->po bf16, scatter)  3=FC1(gelu)  4=QKV merged (y<2: q, else kv)
template <int NTILES, int EPI>
__global__ void __launch_bounds__(256, 2) gemm_ml(const float* __restrict__ bias,
                                                  const float* __restrict__ bias2) {
    extern __shared__ __nv_bfloat16 sm[];
    const uint32_t sA_u[2] = {s2u(sm), s2u(sm) + 32768};
    const uint32_t sB_u = s2u(sm) + 65536;

    const bool isq = (EPI == 4) && (blockIdx.y < 2);
    const __nv_bfloat16* A =
        (EPI == 2) ? g_ao : (EPI == 3) ? g_xon : (isq ? g_xn : g_vn);
    const __nv_bfloat16* W =
        (EPI == 2) ? g_pw : (EPI == 3) ? g_f1w : (isq ? g_qw : g_kvw);
    const float* bptr = (EPI == 4) ? (isq ? bias : bias2) : bias;

    const int tid = threadIdx.x, warp = tid >> 5, lane = tid & 31;
    const int mbase = blockIdx.x * (128 * MIT);
    const int yb = (EPI == 4) ? (isq ? blockIdx.y : blockIdx.y - 2) : blockIdx.y;
    const int n0 = yb * (64 * NTILES);
    const int wm = (warp & 3) * 32, wn = (warp >> 2) * 32;
    const int g = lane >> 2, tg = lane & 3;
    const int a_row = wm + (lane & 15), a_ch = lane >> 4;
    const int b_row = wn + ((lane >> 4) << 3) + (lane & 7), b_ch = (lane >> 3) & 1;

    float breg[NTILES][8];
#pragma unroll
    for (int nt = 0; nt < NTILES; nt++)
#pragma unroll
        for (int ni = 0; ni < 4; ni++)
#pragma unroll
            for (int cc = 0; cc < 2; cc++)
                breg[nt][ni * 2 + cc] =
                    __ldg(bptr + n0 + nt * 64 + wn + ni * 8 + tg * 2 + cc);

#pragma unroll
    for (int i = 0; i < 4 * NTILES; i++) {
        int idx = tid + i * 256;
        int bt = idx >> 10, rem = idx & 1023;
        int row = rem >> 4, c = rem & 15;
        cpasync16(sB_u + bt * 16384 + swoff(row, c),
                  W + (size_t)(n0 + bt * 64 + row) * Cc + c * 8);
    }
#pragma unroll
    for (int i = 0; i < 8; i++) {
        int idx = tid + i * 256;
        int row = idx >> 4, c = idx & 15;
        cpasync16(sA_u[0] + swoff(row, c), A + (size_t)(mbase + row) * Cc + c * 8);
    }
    cpcommit();

    for (int mt = 0; mt < MIT; mt++) {
        cpwait0();
        __syncthreads();
        if (mt + 1 < MIT) {
            const int mn = mbase + (mt + 1) * 128;
#pragma unroll
            for (int i = 0; i < 8; i++) {
                int idx = tid + i * 256;
                int row = idx >> 4, c = idx & 15;
                cpasync16(sA_u[(mt + 1) & 1] + swoff(row, c),
                          A + (size_t)(mn + row) * Cc + c * 8);
            }
            cpcommit();
        }
        const uint32_t sAc = sA_u[mt & 1];
        const int m0 = mbase + mt * 128;

#pragma unroll
        for (int nt = 0; nt < NTILES; nt++) {
            const uint32_t sBc = sB_u + nt * 16384;
            const int nc0 = n0 + nt * 64;

            float acc[2][4][4];
#pragma unroll
            for (int a = 0; a < 2; a++)
#pragma unroll
                for (int b = 0; b < 4; b++)
#pragma unroll
                    for (int c = 0; c < 4; c++) acc[a][b][c] = 0.0f;

#pragma unroll
            for (int kh = 0; kh < 8; kh++) {
                uint32_t a[2][4];
#pragma unroll
                for (int mi = 0; mi < 2; mi++) {
                    int row = a_row + mi * 16;
                    int ch = (2 * kh + a_ch) ^ (row & 7);
                    ldsm4(a[mi][0], a[mi][1], a[mi][2], a[mi][3],
                          sAc + ((uint32_t)row << 8) + (uint32_t)(ch << 4));
                }
                uint32_t b[2][4];
#pragma unroll
                for (int nj = 0; nj < 2; nj++) {
                    int row = b_row + nj * 16;
                    int ch = (2 * kh + b_ch) ^ (row & 7);
                    ldsm4(b[nj][0], b[nj][1], b[nj][2], b[nj][3],
                          sBc + ((uint32_t)row << 8) + (uint32_t)(ch << 4));
                }
#pragma unroll
                for (int mi = 0; mi < 2; mi++)
#pragma unroll
                    for (int ni = 0; ni < 4; ni++) {
                        uint32_t bb[2] = {b[ni >> 1][(ni & 1) * 2],
                                          b[ni >> 1][(ni & 1) * 2 + 1]};
                        mma16816(acc[mi][ni], a[mi], bb);
                    }
            }

#pragma unroll
            for (int mi = 0; mi < 2; mi++)
#pragma unroll
                for (int rr = 0; rr < 2; rr++) {
                    int row = m0 + wm + mi * 16 + g + rr * 8;
                    if (EPI == 4 && isq) {
#pragma unroll
                        for (int ni = 0; ni < 4; ni++) {
                            float v0 = (acc[mi][ni][rr * 2] + breg[nt][ni * 2]) * SCALE;
                            float v1 = (acc[mi][ni][rr * 2 + 1] + breg[nt][ni * 2 + 1]) * SCALE;
                            __nv_bfloat162 p = __float22bfloat162_rn(make_float2(v0, v1));
                            *(uint32_t*)(g_q + (size_t)row * Cc + nc0 + wn + ni * 8 + tg * 2) =
                                *(uint32_t*)&p;
                        }
                    } else if (EPI == 4) {
                        __nv_bfloat16* dst = (nc0 < Cc) ? g_k : g_v;
                        const int nb = (nc0 < Cc) ? nc0 : nc0 - Cc;
#pragma unroll
                        for (int ni = 0; ni < 4; ni++) {
                            float v0 = acc[mi][ni][rr * 2] + breg[nt][ni * 2];
                            float v1 = acc[mi][ni][rr * 2 + 1] + breg[nt][ni * 2 + 1];
                            __nv_bfloat162 p = __float22bfloat162_rn(make_float2(v0, v1));
                            *(uint32_t*)(dst + (size_t)row * Cc + nb + wn + ni * 8 + tg * 2) =
                                *(uint32_t*)&p;
                        }
                    } else if (EPI == 2) {
                        int win = row / NTOK, n = row - win * NTOK;
                        int b = win >> 8, wr = win & 255;
                        int wy = wr >> 4, wx = wr & 15;
                        int iy = n / WS, ix = n - iy * WS;
                        int trow = b * L + (wy * WS + iy) * Wdim + wx * WS + ix;
#pragma unroll
                        for (int ni = 0; ni < 4; ni++) {
                            float v0 = acc[mi][ni][rr * 2] + breg[nt][ni * 2];
                            float v1 = acc[mi][ni][rr * 2 + 1] + breg[nt][ni * 2 + 1];
                            __nv_bfloat162 p = __float22bfloat162_rn(make_float2(v0, v1));
                            *(uint32_t*)(g_po + (size_t)trow * Cc + nc0 + wn + ni * 8 + tg * 2) =
                                *(uint32_t*)&p;
                        }
                    } else {
#pragma unroll
                        for (int ni = 0; ni < 4; ni++) {
                            float v0 = acc[mi][ni][rr * 2] + breg[nt][ni * 2];
                            float v1 = acc[mi][ni][rr * 2 + 1] + breg[nt][ni * 2 + 1];
                            v0 = 0.5f * v0 * (1.0f + erff(v0 * 0.70710678118654752f));
                            v1 = 0.5f * v1 * (1.0f + erff(v1 * 0.70710678118654752f));
                            __nv_bfloat162 p = __float22bfloat162_rn(make_float2(v0, v1));
                            *(uint32_t*)(g_h1 + (size_t)row * MLPH + nc0 + wn + ni * 8 + tg * 2) =
                                *(uint32_t*)&p;
                        }
                    }
                }
        }
    }
}

// ---------------- fc2: full weight resident, out = acc + b2 + x + po ----------------
__global__ void __launch_bounds__(256) gemm_fc2(const float* __restrict__ bias,
                                                const float* __restrict__ xres,
                                                float* __restrict__ outf) {
    extern __shared__ __nv_bfloat16 sm[];
    const uint32_t sA_u[2] = {s2u(sm), s2u(sm) + 32768};
    const uint32_t sB_u = s2u(sm) + 65536;

    const int tid = threadIdx.x, warp = tid >> 5, lane = tid & 31;
    const int mbase = blockIdx.x * (128 * MIT);
    const int wm = (warp & 3) * 32, wn = (warp >> 2) * 32;
    const int g = lane >> 2, tg = lane & 3;
    const int a_row = wm + (lane & 15), a_ch = lane >> 4;
    const int b_row = wn + ((lane >> 4) << 3) + (lane & 7), b_ch = (lane >> 3) & 1;

    float breg[2][8];
#pragma unroll
    for (int nt = 0; nt < 2; nt++)
#pragma unroll
        for (int ni = 0; ni < 4; ni++)
#pragma unroll
            for (int cc = 0; cc < 2; cc++)
                breg[nt][ni * 2 + cc] = __ldg(bias + nt * 64 + wn + ni * 8 + tg * 2 + cc);

#pragma unroll
    for (int i = 0; i < 32; i++) {
        int idx = tid + i * 256;
        int bt = idx >> 10, rem = idx & 1023;
        int kc = bt >> 1, nt = bt & 1;
        int row = rem >> 4, c = rem & 15;
        cpasync16(sB_u + bt * 16384 + swoff(row, c),
                  g_f2w + (size_t)(nt * 64 + row) * MLPH + kc * 128 + c * 8);
    }
#pragma unroll
    for (int i = 0; i < 8; i++) {
        int idx = tid + i * 256;
        int row = idx >> 4, c = idx & 15;
        cpasync16(sA_u[0] + swoff(row, c), g_h1 + (size_t)(mbase + row) * MLPH + c * 8);
    }
    cpcommit();

    float acc[2][2][4][4];
    constexpr int NSTEP = MIT * 4;
    for (int step = 0; step < NSTEP; step++) {
        const int mt = step >> 2, kc = step & 3;
        cpwait0();
        __syncthreads();
        if (step + 1 < NSTEP) {
            const int nmt = (step + 1) >> 2, nkc = (step + 1) & 3;
            const int mrow = mbase + nmt * 128;
#pragma unroll
            for (int i = 0; i < 8; i++) {
                int idx = tid + i * 256;
                int row = idx >> 4, c = idx & 15;
                cpasync16(sA_u[(step + 1) & 1] + swoff(row, c),
                          g_h1 + (size_t)(mrow + row) * MLPH + nkc * 128 + c * 8);
            }
            cpcommit();
        }
        if (kc == 0) {
#pragma unroll
            for (int t = 0; t < 2; t++)
#pragma unroll
                for (int a = 0; a < 2; a++)
#pragma unroll
                    for (int b = 0; b < 4; b++)
#pragma unroll
                        for (int c = 0; c < 4; c++) acc[t][a][b][c] = 0.0f;
        }
        const uint32_t sAc = sA_u[step & 1];

#pragma unroll
        for (int kh = 0; kh < 8; kh++) {
            uint32_t a[2][4];
#pragma unroll
            for (int mi = 0; mi < 2; mi++) {
                int row = a_row + mi * 16;
                int ch = (2 * kh + a_ch) ^ (row & 7);
                ldsm4(a[mi][0], a[mi][1], a[mi][2], a[mi][3],
                      sAc + ((uint32_t)row << 8) + (uint32_t)(ch << 4));
            }
#pragma unroll
            for (int nt = 0; nt < 2; nt++) {
                const uint32_t sBc = sB_u + (kc * 2 + nt) * 16384;
                uint32_t b[2][4];
#pragma unroll
                for (int nj = 0; nj < 2; nj++) {
                    int row = b_row + nj * 16;
                    int ch = (2 * kh + b_ch) ^ (row & 7);
                    ldsm4(b[nj][0], b[nj][1], b[nj][2], b[nj][3],
                          sBc + ((uint32_t)row << 8) + (uint32_t)(ch << 4));
                }
#pragma unroll
                for (int mi = 0; mi < 2; mi++)
#pragma unroll
                    for (int ni = 0; ni < 4; ni++) {
                        uint32_t bb[2] = {b[ni >> 1][(ni & 1) * 2],
                                          b[ni >> 1][(ni & 1) * 2 + 1]};
                        mma16816(acc[nt][mi][ni], a[mi], bb);
                    }
            }
        }

        if (kc == 3) {
            const int m0 = mbase + mt * 128;
#pragma unroll
            for (int nt = 0; nt < 2; nt++)
#pragma unroll
                for (int mi = 0; mi < 2; mi++)
#pragma unroll
                    for (int rr = 0; rr < 2; rr++) {
                        int row = m0 + wm + mi * 16 + g + rr * 8;
#pragma unroll
                        for (int ni = 0; ni < 4; ni++) {
                            size_t oi = (size_t)row * Cc + nt * 64 + wn + ni * 8 + tg * 2;
                            float2 xv = *(const float2*)(xres + oi);
                            __nv_bfloat162 pv = *(const __nv_bfloat162*)(g_po + oi);
                            float2 ov;
                            ov.x = acc[nt][mi][ni][rr * 2] + breg[nt][ni * 2] + xv.x +
                                   __bfloat162float(pv.x);
                            ov.y = acc[nt][mi][ni][rr * 2 + 1] + breg[nt][ni * 2 + 1] + xv.y +
                                   __bfloat162float(pv.y);
                            *(float2*)(outf + oi) = ov;
                        }
                    }
        }
    }
}

// ---------------- tensor-core windowed attention (phased regs + hoisted index algebra) ----------------
__global__ void __launch_bounds__(128) attn_kernel(const float* __restrict__ rpb) {
    constexpr int SST = 136;
    __shared__ __nv_bfloat16 sK[64 * SST];
    __shared__ __nv_bfloat16 sV[64 * SST];
    __shared__ float sb[HEADS * 169];

    const int win = blockIdx.x;
    const int tid = threadIdx.x, warp = tid >> 5, lane = tid & 31;
    const int g = lane >> 2, tg = lane & 3;
    const size_t base = (size_t)win * NTOK * Cc;

    for (int i = tid; i < 49 * 16; i += 128) {
        int r = i >> 4, cb = (i & 15) * 8;
        cpasync16(s2u(&sK[r * SST + cb]), g_k + base + (size_t)r * Cc + cb);
        cpasync16(s2u(&sV[r * SST + cb]), g_v + base + (size_t)r * Cc + cb);
    }
    for (int i = tid; i < 15 * 16; i += 128) {
        int r = 49 + (i >> 4), cb = (i & 15) * 8;
        *(uint4*)&sV[r * SST + cb] = make_uint4(0, 0, 0, 0);
    }
    for (int i = lane; i < 169; i += 32) sb[warp * 169 + i] = rpb[i * HEADS + warp];
    cpcommit();
    cpwait0();
    __syncthreads();

    const int hc = warp * HD;
    const float* sbh = &sb[warp * 169];

    // hoisted key geometry (invariant across mt, rr)
    int koff[14];
    bool msk[14];
#pragma unroll
    for (int j = 0; j < 14; j++) {
        int key = (j >> 1) * 8 + tg * 2 + (j & 1);
        int ky = key / WS, kx = key - ky * WS;
        koff[j] = ky * 13 + kx;
        msk[j] = (key < NTOK);
    }

#pragma unroll
    for (int mt = 0; mt < 4; mt++) {
        uint32_t qa[2][4];
        int q0 = win * NTOK + mt * 16 + g;
        int q1 = q0 + 8;
        int q0c = q0 < T ? q0 : T - 1;
        int q1c = q1 < T ? q1 : T - 1;
#pragma unroll
        for (int kh = 0; kh < 2; kh++) {
            const __nv_bfloat16* p0 = g_q + (size_t)q0c * Cc + hc + kh * 16 + tg * 2;
            const __nv_bfloat16* p1 = g_q + (size_t)q1c * Cc + hc + kh * 16 + tg * 2;
            qa[kh][0] = *(const uint32_t*)p0;
            qa[kh][1] = *(const uint32_t*)p1;
            qa[kh][2] = *(const uint32_t*)(p0 + 8);
            qa[kh][3] = *(const uint32_t*)(p1 + 8);
        }

        float s[7][4];
#pragma unroll
        for (int nt = 0; nt < 7; nt++)
#pragma unroll
            for (int c = 0; c < 4; c++) s[nt][c] = 0.0f;
#pragma unroll
        for (int kh = 0; kh < 2; kh++)
#pragma unroll
            for (int nt = 0; nt < 7; nt++) {
                const __nv_bfloat16* p = &sK[(nt * 8 + g) * SST + hc + kh * 16 + tg * 2];
                uint32_t kb[2];
                kb[0] = *(const uint32_t*)p;
                kb[1] = *(const uint32_t*)(p + 8);
                mma16816(s[nt], qa[kh], kb);
            }

        uint32_t pa[4][4];
#pragma unroll
        for (int rr = 0; rr < 2; rr++) {
            int q = mt * 16 + g + rr * 8;
            int qq = q < NTOK ? q : NTOK - 1;
            int qy = qq / WS, qx = qq - qy * WS;
            const int qbase = (qy + 6) * 13 + (qx + 6);
            float ev[14];
            float mx = -1e30f;
#pragma unroll
            for (int j = 0; j < 14; j++) {
                float v = s[j >> 1][rr * 2 + (j & 1)];
                if (msk[j]) {
                    v += sbh[qbase - koff[j]];
                    mx = fmaxf(mx, v);
                }
                ev[j] = v;
            }
            mx = fmaxf(mx, __shfl_xor_sync(0xffffffffu, mx, 1));
            mx = fmaxf(mx, __shfl_xor_sync(0xffffffffu, mx, 2));
            float sum = 0.0f;
#pragma unroll
            for (int j = 0; j < 14; j++) {
                float e = msk[j] ? __expf(ev[j] - mx) : 0.0f;
                ev[j] = e;
                sum += e;
            }
            sum += __shfl_xor_sync(0xffffffffu, sum, 1);
            sum += __shfl_xor_sync(0xffffffffu, sum, 2);
            float inv = __fdividef(1.0f, sum);
#pragma unroll
            for (int kt = 0; kt < 4; kt++) {
                int ntA = 2 * kt, ntB = 2 * kt + 1;
                __nv_bfloat162 pA = __float22bfloat162_rn(
                    make_float2(ev[ntA * 2] * inv, ev[ntA * 2 + 1] * inv));
                pa[kt][rr] = *(uint32_t*)&pA;
                if (ntB < 7) {
                    __nv_bfloat162 pB = __float22bfloat162_rn(
                        make_float2(ev[ntB * 2] * inv, ev[ntB * 2 + 1] * inv));
                    pa[kt][2 + rr] = *(uint32_t*)&pB;
                } else {
                    pa[kt][2 + rr] = 0u;
                }
            }
        }

        float o[4][4];
#pragma unroll
        for (int nd = 0; nd < 4; nd++)
#pragma unroll
            for (int c = 0; c < 4; c++) o[nd][c] = 0.0f;
#pragma unroll
        for (int kt = 0; kt < 4; kt++)
#pragma unroll
            for (int nd = 0; nd < 4; nd++) {
                int k0 = kt * 16 + tg * 2;
                int c = hc + nd * 8 + g;
                __nv_bfloat162 b0 = {sV[k0 * SST + c], sV[(k0 + 1) * SST + c]};
                __nv_bfloat162 b1 = {sV[(k0 + 8) * SST + c], sV[(k0 + 9) * SST + c]};
                uint32_t vb[2];
                vb[0] = *(uint32_t*)&b0;
                vb[1] = *(uint32_t*)&b1;
                mma16816(o[nd], pa[kt], vb);
            }

#pragma unroll
        for (int rr = 0; rr < 2; rr++) {
            int q = mt * 16 + g + rr * 8;
            if (q < NTOK) {
#pragma unroll
                for (int nd = 0; nd < 4; nd++) {
                    __nv_bfloat162 p2 = __float22bfloat162_rn(
                        make_float2(o[nd][rr * 2], o[nd][rr * 2 + 1]));
                    *(uint32_t*)(g_ao + base + (size_t)q * Cc + hc + nd * 8 + tg * 2) =
                        *(uint32_t*)&p2;
                }
            }
        }
    }
}

// ---------------- launch ----------------
extern "C" void kernel_launch(void* const* d_in, const int* in_sizes, int n_in,
                              void* d_out, int out_size) {
    const float* x   = (const float*)d_in[0];
    const float* v   = (const float*)d_in[1];
    const float* n1g = (const float*)d_in[2];
    const float* n1b = (const float*)d_in[3];
    const float* nvg = (const float*)d_in[4];
    const float* nvb = (const float*)d_in[5];
    const float* qw  = (const float*)d_in[6];
    const float* qb  = (const float*)d_in[7];
    const float* kvw = (const float*)d_in[8];
    const float* kvb = (const float*)d_in[9];
    const float* rpb = (const float*)d_in[10];
    const float* pw  = (const float*)d_in[11];
    const float* pb  = (const float*)d_in[12];
    const float* n2g = (const float*)d_in[13];
    const float* n2b = (const float*)d_in[14];
    const float* f1w = (const float*)d_in[15];
    const float* f1b = (const float*)d_in[16];
    const float* f2w = (const float*)d_in[17];
    const float* f2b = (const float*)d_in[18];
    float* out = (float*)d_out;

    constexpr int GX = T / (128 * MIT);          // 392
    constexpr int ML1_SMEM = 80 * 1024;
    constexpr int ML2_SMEM = 96 * 1024;
    constexpr int FC2_SMEM = 192 * 1024;
    cudaFuncSetAttribute(gemm_ml<1, 4>, cudaFuncAttributeMaxDynamicSharedMemorySize, ML1_SMEM);
    cudaFuncSetAttribute(gemm_ml<1, 2>, cudaFuncAttributeMaxDynamicSharedMemorySize, ML1_SMEM);
    cudaFuncSetAttribute(gemm_ml<2, 3>, cudaFuncAttributeMaxDynamicSharedMemorySize, ML2_SMEM);
    cudaFuncSetAttribute(gemm_fc2, cudaFuncAttributeMaxDynamicSharedMemorySize, FC2_SMEM);

    cvt_all<<<(Cc * MLPH + 255) / 256, 256>>>(qw, kvw, pw, f1w, f2w);
    ln1_kernel<<<T / 8, 256>>>(x, v, n1g, n1b, nvg, nvb);
    gemm_ml<1, 4><<<dim3(GX, 6), 256, ML1_SMEM>>>(qb, kvb);          // q + kv merged
    attn_kernel<<<NWIN, 128>>>(rpb);
    gemm_ml<1, 2><<<dim3(GX, 2), 256, ML1_SMEM>>>(pb, nullptr);      // proj -> po
    ln2_kernel<<<T / 8, 256>>>(x, n2g, n2b);                         // LN(x + po)
    gemm_ml<2, 3><<<dim3(GX, 4), 256, ML2_SMEM>>>(f1b, nullptr);     // fc1 + gelu
    gemm_fc2<<<GX, 256, FC2_SMEM>>>(f2b, x, out);                    // fc2 + x + po
}